// round 4
// baseline (speedup 1.0000x reference)
#include <cuda_runtime.h>
#include <cuda_bf16.h>
#include <cstdint>

#define HD   1024
#define TT   512
#define BB   64
#define IND  512
#define BT   32768            // BB*TT
#define GCTA 128              // scan CTAs
#define XG   33554432ull      // TT*BB*HD (per-gate xbuf stride)

// ---------------- device scratch (no allocs allowed) ----------------------
__device__ __align__(16) __nv_bfloat16 g_xhi[(size_t)BT * IND];
__device__ __align__(16) __nv_bfloat16 g_xlo[(size_t)BT * IND];
__device__ __align__(16) __nv_bfloat16 g_wxhi[3u * HD * IND];
__device__ __align__(16) __nv_bfloat16 g_wxlo[3u * HD * IND];
__device__ __align__(16) __nv_bfloat16 g_whhi[3u * HD * HD];
__device__ __align__(16) __nv_bfloat16 g_whlo[3u * HD * HD];
__device__ __align__(16) float         g_xbuf[3ull * TT * BB * HD];   // [gate][t][b][h]
__device__ __align__(16) __nv_bfloat16 g_hh[2 * BB * HD];             // h split, double buf
__device__ __align__(16) __nv_bfloat16 g_hl[2 * BB * HD];
__device__ unsigned g_cnt;
__device__ unsigned g_gen;

// ---------------- helpers -------------------------------------------------
__device__ __forceinline__ uint32_t lds32(const __nv_bfloat16* p) {
    return *(const uint32_t*)p;
}

__device__ __forceinline__ void mma_bf16(float c[4], const uint32_t a[4], const uint32_t b[2]) {
    asm volatile(
        "mma.sync.aligned.m16n8k16.row.col.f32.bf16.bf16.f32 "
        "{%0,%1,%2,%3}, {%4,%5,%6,%7}, {%8,%9}, {%0,%1,%2,%3};\n"
        : "+f"(c[0]), "+f"(c[1]), "+f"(c[2]), "+f"(c[3])
        : "r"(a[0]), "r"(a[1]), "r"(a[2]), "r"(a[3]), "r"(b[0]), "r"(b[1]));
}

__device__ __forceinline__ void gridbar(unsigned target) {
    __syncthreads();
    if (threadIdx.x == 0) {
        __threadfence();
        unsigned a = atomicAdd(&g_cnt, 1u);
        if (a == GCTA - 1u) {
            atomicExch(&g_cnt, 0u);
            __threadfence();
            atomicAdd(&g_gen, 1u);
        } else {
            while (atomicAdd(&g_gen, 0u) < target) __nanosleep(64);
        }
        __threadfence();
    }
    __syncthreads();
}

// ---------------- prep: fp32 -> bf16 hi/lo split --------------------------
__global__ void k_prep(const float* __restrict__ x,
                       const float* __restrict__ wxr, const float* __restrict__ wxz,
                       const float* __restrict__ wxn,
                       const float* __restrict__ whr, const float* __restrict__ whz,
                       const float* __restrict__ whn) {
    const unsigned N0 = (unsigned)BT * IND;     // 16777216
    const unsigned N1 = HD * IND;               // 524288
    const unsigned N2 = HD * HD;                // 1048576
    const unsigned TOT = N0 + 3u * N1 + 3u * N2;
    for (unsigned i = blockIdx.x * blockDim.x + threadIdx.x; i < TOT;
         i += gridDim.x * blockDim.x) {
        float v;
        __nv_bfloat16 *dh, *dl;
        unsigned j;
        if (i < N0) {
            v = x[i]; dh = g_xhi; dl = g_xlo; j = i;
        } else if (i < N0 + 3u * N1) {
            unsigned k = i - N0;
            unsigned gi = k / N1;
            const float* s = (gi == 0) ? wxr : (gi == 1) ? wxz : wxn;
            v = s[k - gi * N1]; dh = g_wxhi; dl = g_wxlo; j = k;
        } else {
            unsigned k = i - N0 - 3u * N1;
            unsigned gi = k / N2;
            const float* s = (gi == 0) ? whr : (gi == 1) ? whz : whn;
            v = s[k - gi * N2]; dh = g_whhi; dl = g_whlo; j = k;
        }
        __nv_bfloat16 hi = __float2bfloat16_rn(v);
        float lo = v - __bfloat162float(hi);
        dh[j] = hi;
        dl[j] = __float2bfloat16_rn(lo);
    }
}

// ---------------- phase 1: input projections ------------------------------
// grid (16 n-tiles, 512 m-tiles, 3 gates), block 256 (8 warps: 4m x 2n)
// CTA tile 64x64, warp tile m16 x n32 (4 n8 sub-tiles), K = 512.
__global__ __launch_bounds__(256, 1)
void k_proj(const float* __restrict__ br, const float* __restrict__ bz,
            const float* __restrict__ bn) {
    __shared__ __nv_bfloat16 sAh[64 * 72], sAl[64 * 72], sBh[64 * 72], sBl[64 * 72];

    const int tid = threadIdx.x;
    const int gate = blockIdx.z;
    const unsigned m0 = blockIdx.y * 64u;
    const unsigned n0 = blockIdx.x * 64u;
    const __nv_bfloat16* Wh = g_wxhi + (size_t)gate * HD * IND;
    const __nv_bfloat16* Wl = g_wxlo + (size_t)gate * HD * IND;
    const float* bias = (gate == 0) ? br : (gate == 1) ? bz : bn;

    const int w = tid >> 5, l = tid & 31;
    const int mw = w & 3, wn = w >> 2;
    const int gq = l >> 2, tg = l & 3;

    float acc[4][4];
#pragma unroll
    for (int i = 0; i < 4; i++)
#pragma unroll
        for (int j = 0; j < 4; j++) acc[i][j] = 0.f;

    for (int kc = 0; kc < IND; kc += 64) {
        __syncthreads();
        // stage 4 arrays x (64 rows x 64 bf16) = 4 x 512 16B-loads
#pragma unroll
        for (int q = 0; q < 8; q++) {
            int u = tid + q * 256;           // 0..2047
            int arr = u >> 9, v = u & 511;
            int row = v >> 3, c8 = v & 7;
            const uint4* src;
            __nv_bfloat16* dst;
            if (arr == 0) { src = (const uint4*)(g_xhi + (size_t)(m0 + row) * IND + kc + c8 * 8); dst = sAh; }
            else if (arr == 1) { src = (const uint4*)(g_xlo + (size_t)(m0 + row) * IND + kc + c8 * 8); dst = sAl; }
            else if (arr == 2) { src = (const uint4*)(Wh + (size_t)(n0 + row) * IND + kc + c8 * 8); dst = sBh; }
            else { src = (const uint4*)(Wl + (size_t)(n0 + row) * IND + kc + c8 * 8); dst = sBl; }
            *(uint4*)(dst + row * 72 + c8 * 8) = *src;
        }
        __syncthreads();
#pragma unroll
        for (int kk = 0; kk < 64; kk += 16) {
            const int ra = (mw * 16 + gq) * 72 + kk + tg * 2;
            uint32_t ah[4], al[4];
            ah[0] = lds32(sAh + ra);          ah[1] = lds32(sAh + ra + 8 * 72);
            ah[2] = lds32(sAh + ra + 8);      ah[3] = lds32(sAh + ra + 8 * 72 + 8);
            al[0] = lds32(sAl + ra);          al[1] = lds32(sAl + ra + 8 * 72);
            al[2] = lds32(sAl + ra + 8);      al[3] = lds32(sAl + ra + 8 * 72 + 8);
#pragma unroll
            for (int t8 = 0; t8 < 4; t8++) {
                const int rb = (wn * 32 + t8 * 8 + gq) * 72 + kk + tg * 2;
                uint32_t bh[2] = { lds32(sBh + rb), lds32(sBh + rb + 8) };
                uint32_t bl[2] = { lds32(sBl + rb), lds32(sBl + rb + 8) };
                mma_bf16(acc[t8], ah, bh);
                mma_bf16(acc[t8], ah, bl);
                mma_bf16(acc[t8], al, bh);
            }
        }
    }

    // store to g_xbuf[gate][t][b][h], bias fused
#pragma unroll
    for (int t8 = 0; t8 < 4; t8++) {
        unsigned col = n0 + wn * 32 + t8 * 8 + tg * 2;
        float b0 = bias[col], b1 = bias[col + 1];
        unsigned r0 = m0 + mw * 16 + gq;
        {
            unsigned b = r0 >> 9, tl = r0 & 511;
            float* o = g_xbuf + (size_t)gate * XG + (((size_t)tl * 64 + b) << 10) + col;
            o[0] = acc[t8][0] + b0;
            o[1] = acc[t8][1] + b1;
        }
        {
            unsigned r1 = r0 + 8;
            unsigned b = r1 >> 9, tl = r1 & 511;
            float* o = g_xbuf + (size_t)gate * XG + (((size_t)tl * 64 + b) << 10) + col;
            o[0] = acc[t8][2] + b0;
            o[1] = acc[t8][3] + b1;
        }
    }
}

// ---------------- barrier init (each replay) ------------------------------
__global__ void k_init() { g_cnt = 0u; g_gen = 0u; }

// ---------------- phase 2: persistent recurrence --------------------------
// 128 CTAs x 384 threads (12 warps). CTA owns 8 h-cols -> N=24 (3 gates x 8).
// Warp (mt = w&3, gate = w>>2) computes one m16n8 tile over K=1024.
// Wh slice (hi/lo) resident in smem. A (h_{t-1}) staged per 128-col chunk.
#define SW_STRIDE 1032
#define SA_STRIDE 136
#define SA_ELEMS  (64 * SA_STRIDE)          // 8704
#define SMEM_SCAN (2*24*SW_STRIDE*2 + 4*SA_ELEMS*2 + 3*64*8*4)  // 174848 B

__device__ __forceinline__ void stage_chunk(const __nv_bfloat16* __restrict__ Hh,
                                            const __nv_bfloat16* __restrict__ Hl,
                                            __nv_bfloat16* sA, int buf, int kc, int tid) {
    for (int u = tid; u < 2048; u += 384) {
        int arr = u >> 10, v = u & 1023;
        int row = v >> 4, c = v & 15;
        const uint4* src = (const uint4*)((arr ? Hl : Hh) + (size_t)row * HD + kc + c * 8);
        uint4 d = __ldcg(src);
        *(uint4*)(sA + (size_t)(buf * 2 + arr) * SA_ELEMS + row * SA_STRIDE + c * 8) = d;
    }
}

__global__ __launch_bounds__(384, 1)
void k_scan(float* __restrict__ out_last, float* __restrict__ out_hs) {
    extern __shared__ char smem[];
    __nv_bfloat16* sWh = (__nv_bfloat16*)smem;                 // 24 x 1032
    __nv_bfloat16* sWl = sWh + 24 * SW_STRIDE;
    __nv_bfloat16* sA  = sWl + 24 * SW_STRIDE;                 // [2 buf][2 hl][64*136]
    float* sAcc = (float*)(sA + 4 * SA_ELEMS);                 // [3][64][8]

    const int tid = threadIdx.x;
    const int w = tid >> 5, l = tid & 31;
    const int mt = w & 3, gate = w >> 2;
    const int gq = l >> 2, tg = l & 3;
    const unsigned h0 = blockIdx.x * 8u;

    // load this CTA's Wh hi/lo slice once (24 rows x 1024)
    for (int u = tid; u < 6144; u += 384) {
        int arr = (u >= 3072);
        int v = arr ? (u - 3072) : u;
        int r = v >> 7, c16 = v & 127;
        size_t grow = (size_t)(r >> 3) * HD + h0 + (r & 7);    // gate*HD + col
        const uint4* src = (const uint4*)((arr ? g_whlo : g_whhi) + grow * HD + c16 * 8);
        __nv_bfloat16* dst = (arr ? sWl : sWh) + r * SW_STRIDE + c16 * 8;
        *(uint4*)dst = *src;
    }
    __syncthreads();

    const int brow = (gate * 8 + gq) * SW_STRIDE + tg * 2;     // B base for this warp

    for (int t = 0; t < TT; t++) {
        float c0[4] = {0.f, 0.f, 0.f, 0.f};     // hi*hi + lo*hi chain
        float c1[4] = {0.f, 0.f, 0.f, 0.f};     // hi*lo chain

        if (t > 0) {
            const int p = (t - 1) & 1;
            const __nv_bfloat16* Hh = g_hh + p * BB * HD;
            const __nv_bfloat16* Hl = g_hl + p * BB * HD;
            stage_chunk(Hh, Hl, sA, 0, 0, tid);
            __syncthreads();
            for (int ch = 0; ch < 8; ch++) {
                const int buf = ch & 1;
                if (ch < 7) stage_chunk(Hh, Hl, sA, buf ^ 1, (ch + 1) * 128, tid);
                const __nv_bfloat16* Ah = sA + (size_t)(buf * 2) * SA_ELEMS;
                const __nv_bfloat16* Al = Ah + SA_ELEMS;
#pragma unroll
                for (int kk = 0; kk < 128; kk += 16) {
                    const int ra = (mt * 16 + gq) * SA_STRIDE + kk + tg * 2;
                    uint32_t ah[4], al[4];
                    ah[0] = lds32(Ah + ra);         ah[1] = lds32(Ah + ra + 8 * SA_STRIDE);
                    ah[2] = lds32(Ah + ra + 8);     ah[3] = lds32(Ah + ra + 8 * SA_STRIDE + 8);
                    al[0] = lds32(Al + ra);         al[1] = lds32(Al + ra + 8 * SA_STRIDE);
                    al[2] = lds32(Al + ra + 8);     al[3] = lds32(Al + ra + 8 * SA_STRIDE + 8);
                    const int rb = brow + ch * 128 + kk;
                    uint32_t bh[2] = { lds32(sWh + rb), lds32(sWh + rb + 8) };
                    uint32_t bl[2] = { lds32(sWl + rb), lds32(sWl + rb + 8) };
                    mma_bf16(c0, ah, bh);
                    mma_bf16(c1, ah, bl);
                    mma_bf16(c0, al, bh);
                }
                __syncthreads();
            }
        }

        // stash accumulators: sAcc[gate][b][c]
        {
            const int r0 = mt * 16 + gq;
            sAcc[gate * 512 + r0 * 8 + tg * 2]           = c0[0] + c1[0];
            sAcc[gate * 512 + r0 * 8 + tg * 2 + 1]       = c0[1] + c1[1];
            sAcc[gate * 512 + (r0 + 8) * 8 + tg * 2]     = c0[2] + c1[2];
            sAcc[gate * 512 + (r0 + 8) * 8 + tg * 2 + 1] = c0[3] + c1[3];
        }
        __syncthreads();

        // fused gates + h update for the CTA's 64 x 8 elements
        for (int idx = tid; idx < 512; idx += 384) {
            const int b = idx >> 3, c = idx & 7;
            const int h = h0 + c;
            const size_t xo = (((size_t)t * 64 + b) << 10) + h;
            const float xr = g_xbuf[xo];
            const float xz = g_xbuf[XG + xo];
            const float xn = g_xbuf[2 * XG + xo];
            const float ar = sAcc[b * 8 + c];
            const float az = sAcc[512 + b * 8 + c];
            const float an = sAcc[1024 + b * 8 + c];
            float hp = 0.f;
            if (t > 0) hp = __ldcg(out_hs + ((size_t)b * TT + (t - 1)) * HD + h);
            const float r = 1.f / (1.f + __expf(-(xr + ar)));
            const float z = 1.f / (1.f + __expf(-(xz + az)));
            const float nn = tanhf(xn + r * an);
            const float hn = (1.f - z) * nn + z * hp;
            out_hs[((size_t)b * TT + t) * HD + h] = hn;
            const __nv_bfloat16 hi = __float2bfloat16_rn(hn);
            const float lo = hn - __bfloat162float(hi);
            const int p = t & 1;
            g_hh[p * BB * HD + b * HD + h] = hi;
            g_hl[p * BB * HD + b * HD + h] = __float2bfloat16_rn(lo);
            if (t == TT - 1) out_last[b * HD + h] = hn;
        }

        gridbar((unsigned)(t + 1));
    }
}

// ---------------- launcher ------------------------------------------------
extern "C" void kernel_launch(void* const* d_in, const int* in_sizes, int n_in,
                              void* d_out, int out_size) {
    const float* x   = (const float*)d_in[0];
    const float* wxr = (const float*)d_in[1];
    const float* bxr = (const float*)d_in[2];
    const float* whr = (const float*)d_in[3];
    const float* wxz = (const float*)d_in[4];
    const float* bxz = (const float*)d_in[5];
    const float* whz = (const float*)d_in[6];
    const float* wxn = (const float*)d_in[7];
    const float* bxn = (const float*)d_in[8];
    const float* whn = (const float*)d_in[9];

    float* out      = (float*)d_out;
    float* out_last = out;                 // [64,1024]
    float* out_hs   = out + 64 * 1024;     // [64,512,1024]

    cudaFuncSetAttribute(k_scan, cudaFuncAttributeMaxDynamicSharedMemorySize, SMEM_SCAN);

    k_prep<<<1024, 256>>>(x, wxr, wxz, wxn, whr, whz, whn);
    k_proj<<<dim3(16, 512, 3), 256>>>(bxr, bxz, bxn);
    k_init<<<1, 1>>>();
    k_scan<<<GCTA, 384, SMEM_SCAN>>>(out_last, out_hs);
}

// round 6
// speedup vs baseline: 2.0611x; 2.0611x over previous
#include <cuda_runtime.h>
#include <cuda_bf16.h>
#include <cstdint>

#define HD   1024
#define TT   512
#define BB   64
#define IND  512
#define BT   32768            // BB*TT
#define GCTA 128              // scan CTAs
#define XG   33554432ull      // TT*BB*HD (per-gate xbuf stride)

// ---------------- device scratch (no allocs allowed) ----------------------
__device__ __align__(16) __nv_bfloat16 g_xhi[(size_t)BT * IND];
__device__ __align__(16) __nv_bfloat16 g_xlo[(size_t)BT * IND];
__device__ __align__(16) __nv_bfloat16 g_wxhi[3u * HD * IND];
__device__ __align__(16) __nv_bfloat16 g_wxlo[3u * HD * IND];
__device__ __align__(16) __nv_bfloat16 g_whhi[3u * HD * HD];
__device__ __align__(16) __nv_bfloat16 g_whlo[3u * HD * HD];
__device__ __align__(16) float         g_xbuf[3ull * TT * BB * HD];   // [gate][t][b][h]
__device__ __align__(16) __nv_bfloat16 g_hh[2 * BB * HD];             // h split, double buf
__device__ __align__(16) __nv_bfloat16 g_hl[2 * BB * HD];
__device__ unsigned g_cnt;                                            // monotonic barrier counter

// ---------------- helpers -------------------------------------------------
__device__ __forceinline__ uint32_t lds32(const __nv_bfloat16* p) {
    return *(const uint32_t*)p;
}

__device__ __forceinline__ void mma_bf16(float c[4], const uint32_t a[4], const uint32_t b[2]) {
    asm volatile(
        "mma.sync.aligned.m16n8k16.row.col.f32.bf16.bf16.f32 "
        "{%0,%1,%2,%3}, {%4,%5,%6,%7}, {%8,%9}, {%0,%1,%2,%3};\n"
        : "+f"(c[0]), "+f"(c[1]), "+f"(c[2]), "+f"(c[3])
        : "r"(a[0]), "r"(a[1]), "r"(a[2]), "r"(a[3]), "r"(b[0]), "r"(b[1]));
}

// monotonic barrier, all returning RMWs (R4-proven primitives).
// target = GCTA*(t+1); strict: count < GCTA*(t+1) until all arrive at step t.
__device__ __forceinline__ void gridbar(unsigned target) {
    __syncthreads();
    if (threadIdx.x == 0) {
        __threadfence();
        atomicAdd(&g_cnt, 1u);
        while (atomicAdd(&g_cnt, 0u) < target) { }
        __threadfence();
    }
    __syncthreads();
}

// ---------------- prep: fp32 -> bf16 hi/lo split --------------------------
__global__ void k_prep(const float* __restrict__ x,
                       const float* __restrict__ wxr, const float* __restrict__ wxz,
                       const float* __restrict__ wxn,
                       const float* __restrict__ whr, const float* __restrict__ whz,
                       const float* __restrict__ whn) {
    const unsigned N0 = (unsigned)BT * IND;
    const unsigned N1 = HD * IND;
    const unsigned N2 = HD * HD;
    const unsigned TOT = N0 + 3u * N1 + 3u * N2;
    for (unsigned i = blockIdx.x * blockDim.x + threadIdx.x; i < TOT;
         i += gridDim.x * blockDim.x) {
        float v;
        __nv_bfloat16 *dh, *dl;
        unsigned j;
        if (i < N0) {
            v = x[i]; dh = g_xhi; dl = g_xlo; j = i;
        } else if (i < N0 + 3u * N1) {
            unsigned k = i - N0;
            unsigned gi = k / N1;
            const float* s = (gi == 0) ? wxr : (gi == 1) ? wxz : wxn;
            v = s[k - gi * N1]; dh = g_wxhi; dl = g_wxlo; j = k;
        } else {
            unsigned k = i - N0 - 3u * N1;
            unsigned gi = k / N2;
            const float* s = (gi == 0) ? whr : (gi == 1) ? whz : whn;
            v = s[k - gi * N2]; dh = g_whhi; dl = g_whlo; j = k;
        }
        __nv_bfloat16 hi = __float2bfloat16_rn(v);
        float lo = v - __bfloat162float(hi);
        dh[j] = hi;
        dl[j] = __float2bfloat16_rn(lo);
    }
}

// ---------------- phase 1: input projections (unchanged, passing) ---------
__global__ __launch_bounds__(256, 1)
void k_proj(const float* __restrict__ br, const float* __restrict__ bz,
            const float* __restrict__ bn) {
    __shared__ __nv_bfloat16 sAh[64 * 72], sAl[64 * 72], sBh[64 * 72], sBl[64 * 72];

    const int tid = threadIdx.x;
    const int gate = blockIdx.z;
    const unsigned m0 = blockIdx.y * 64u;
    const unsigned n0 = blockIdx.x * 64u;
    const __nv_bfloat16* Wh = g_wxhi + (size_t)gate * HD * IND;
    const __nv_bfloat16* Wl = g_wxlo + (size_t)gate * HD * IND;
    const float* bias = (gate == 0) ? br : (gate == 1) ? bz : bn;

    const int w = tid >> 5, l = tid & 31;
    const int mw = w & 3, wn = w >> 2;
    const int gq = l >> 2, tg = l & 3;

    float acc[4][4];
#pragma unroll
    for (int i = 0; i < 4; i++)
#pragma unroll
        for (int j = 0; j < 4; j++) acc[i][j] = 0.f;

    for (int kc = 0; kc < IND; kc += 64) {
        __syncthreads();
#pragma unroll
        for (int q = 0; q < 8; q++) {
            int u = tid + q * 256;
            int arr = u >> 9, v = u & 511;
            int row = v >> 3, c8 = v & 7;
            const uint4* src;
            __nv_bfloat16* dst;
            if (arr == 0) { src = (const uint4*)(g_xhi + (size_t)(m0 + row) * IND + kc + c8 * 8); dst = sAh; }
            else if (arr == 1) { src = (const uint4*)(g_xlo + (size_t)(m0 + row) * IND + kc + c8 * 8); dst = sAl; }
            else if (arr == 2) { src = (const uint4*)(Wh + (size_t)(n0 + row) * IND + kc + c8 * 8); dst = sBh; }
            else { src = (const uint4*)(Wl + (size_t)(n0 + row) * IND + kc + c8 * 8); dst = sBl; }
            *(uint4*)(dst + row * 72 + c8 * 8) = *src;
        }
        __syncthreads();
#pragma unroll
        for (int kk = 0; kk < 64; kk += 16) {
            const int ra = (mw * 16 + gq) * 72 + kk + tg * 2;
            uint32_t ah[4], al[4];
            ah[0] = lds32(sAh + ra);          ah[1] = lds32(sAh + ra + 8 * 72);
            ah[2] = lds32(sAh + ra + 8);      ah[3] = lds32(sAh + ra + 8 * 72 + 8);
            al[0] = lds32(sAl + ra);          al[1] = lds32(sAl + ra + 8 * 72);
            al[2] = lds32(sAl + ra + 8);      al[3] = lds32(sAl + ra + 8 * 72 + 8);
#pragma unroll
            for (int t8 = 0; t8 < 4; t8++) {
                const int rb = (wn * 32 + t8 * 8 + gq) * 72 + kk + tg * 2;
                uint32_t bh[2] = { lds32(sBh + rb), lds32(sBh + rb + 8) };
                uint32_t bl[2] = { lds32(sBl + rb), lds32(sBl + rb + 8) };
                mma_bf16(acc[t8], ah, bh);
                mma_bf16(acc[t8], ah, bl);
                mma_bf16(acc[t8], al, bh);
            }
        }
    }

#pragma unroll
    for (int t8 = 0; t8 < 4; t8++) {
        unsigned col = n0 + wn * 32 + t8 * 8 + tg * 2;
        float b0 = bias[col], b1 = bias[col + 1];
        unsigned r0 = m0 + mw * 16 + gq;
        {
            unsigned b = r0 >> 9, tl = r0 & 511;
            float* o = g_xbuf + (size_t)gate * XG + (((size_t)tl * 64 + b) << 10) + col;
            o[0] = acc[t8][0] + b0;
            o[1] = acc[t8][1] + b1;
        }
        {
            unsigned r1 = r0 + 8;
            unsigned b = r1 >> 9, tl = r1 & 511;
            float* o = g_xbuf + (size_t)gate * XG + (((size_t)tl * 64 + b) << 10) + col;
            o[0] = acc[t8][2] + b0;
            o[1] = acc[t8][3] + b1;
        }
    }
}

// ---------------- barrier init (each replay) ------------------------------
__global__ void k_init() { g_cnt = 0u; }

// ---------------- phase 2: persistent recurrence --------------------------
// 128 CTAs x 256 threads (8 warps). CTA owns 8 h-cols -> N=24 (3 gates x 8).
// Warp (mt = w&3, ks = w>>2): m16 rows mt*16.., n=24 (all gates), k-half ks.
// k-split is WITHIN each chunk (kk 0-63 / 64-127) so all warps are active on
// every chunk. Cross-warp k-reduction via 2 sAcc slots, summed in epilogue.
#define SW_STRIDE 1032
#define SA_STRIDE 136
#define SA_ELEMS  (64 * SA_STRIDE)          // 8704

// smem: W hi/lo (24x1032 x2 x2B) + A (2buf x 2 x 64x136 x2B) + acc[2][3][512] + hprev
#define SMEM_SCAN (2*24*SW_STRIDE*2 + 4*SA_ELEMS*2 + 2*3*512*4 + 512*4)

// staging: 64 rows x 128 cols x {hi,lo} = 2048 uint4 loads, 8 per thread.
__device__ __forceinline__ void stage_load(const __nv_bfloat16* __restrict__ Hh,
                                           const __nv_bfloat16* __restrict__ Hl,
                                           uint4 r[8], int kc, int tid) {
#pragma unroll
    for (int q = 0; q < 8; q++) {
        int u = tid + q * 256;
        int arr = u >> 10, v = u & 1023;
        int row = v >> 4, c = v & 15;
        r[q] = __ldcg((const uint4*)((arr ? Hl : Hh) + (size_t)row * HD + kc + c * 8));
    }
}

__device__ __forceinline__ void stage_store(const uint4 r[8], __nv_bfloat16* sA,
                                            int buf, int tid) {
#pragma unroll
    for (int q = 0; q < 8; q++) {
        int u = tid + q * 256;
        int arr = u >> 10, v = u & 1023;
        int row = v >> 4, c = v & 15;
        *(uint4*)(sA + (size_t)(buf * 2 + arr) * SA_ELEMS + row * SA_STRIDE + c * 8) = r[q];
    }
}

__global__ __launch_bounds__(256, 1)
void k_scan(float* __restrict__ out_last, float* __restrict__ out_hs) {
    extern __shared__ char smem[];
    __nv_bfloat16* sWh = (__nv_bfloat16*)smem;                 // 24 x 1032
    __nv_bfloat16* sWl = sWh + 24 * SW_STRIDE;
    __nv_bfloat16* sA  = sWl + 24 * SW_STRIDE;                 // [2 buf][2 hl][64*136]
    float* sAcc = (float*)(sA + 4 * SA_ELEMS);                 // [2 ks][3 gate][64][8]
    float* sH   = sAcc + 2 * 3 * 512;                          // h_prev slice [64][8]

    const int tid = threadIdx.x;
    const int w = tid >> 5, l = tid & 31;
    const int mt = w & 3, ks = w >> 2;       // m-tile, k-half
    const int gq = l >> 2, tg = l & 3;
    const unsigned h0 = blockIdx.x * 8u;

    // load this CTA's Wh hi/lo slice once (24 rows x 1024)
    for (int u = tid; u < 6144; u += 256) {
        int arr = (u >= 3072);
        int v = arr ? (u - 3072) : u;
        int r = v >> 7, c16 = v & 127;
        size_t grow = (size_t)(r >> 3) * HD + h0 + (r & 7);    // gate*HD + col
        const uint4* src = (const uint4*)((arr ? g_whlo : g_whhi) + grow * HD + c16 * 8);
        __nv_bfloat16* dst = (arr ? sWl : sWh) + r * SW_STRIDE + c16 * 8;
        *(uint4*)dst = *src;
    }
    __syncthreads();

    const int kbase = ks * 64;               // within-chunk kk offset for this warp

    for (int t = 0; t < TT; t++) {
        // ---- prefetch x-gate values (latency hidden behind MMA loop) ----
        float pxr[2], pxz[2], pxn[2];
#pragma unroll
        for (int q = 0; q < 2; q++) {
            const int idx = tid + q * 256;
            const size_t xo = (((size_t)t * 64 + (idx >> 3)) << 10) + h0 + (idx & 7);
            pxr[q] = g_xbuf[xo];
            pxz[q] = g_xbuf[XG + xo];
            pxn[q] = g_xbuf[2 * XG + xo];
        }

        float c0[3][4], c1[3][4];
#pragma unroll
        for (int g = 0; g < 3; g++)
#pragma unroll
            for (int j = 0; j < 4; j++) { c0[g][j] = 0.f; c1[g][j] = 0.f; }

        if (t > 0) {
            const int p = (t - 1) & 1;
            const __nv_bfloat16* Hh = g_hh + p * BB * HD;
            const __nv_bfloat16* Hl = g_hl + p * BB * HD;
            uint4 r[8];
            stage_load(Hh, Hl, r, 0, tid);
            stage_store(r, sA, 0, tid);
            __syncthreads();
            for (int ch = 0; ch < 8; ch++) {
                const int buf = ch & 1;
                if (ch < 7) stage_load(Hh, Hl, r, (ch + 1) * 128, tid);  // hidden behind compute
                const __nv_bfloat16* Ah = sA + (size_t)(buf * 2) * SA_ELEMS;
                const __nv_bfloat16* Al = Ah + SA_ELEMS;
#pragma unroll
                for (int kk2 = 0; kk2 < 64; kk2 += 16) {
                    const int kk = kbase + kk2;
                    const int ra = (mt * 16 + gq) * SA_STRIDE + kk + tg * 2;
                    uint32_t ah[4], al[4];
                    ah[0] = lds32(Ah + ra);         ah[1] = lds32(Ah + ra + 8 * SA_STRIDE);
                    ah[2] = lds32(Ah + ra + 8);     ah[3] = lds32(Ah + ra + 8 * SA_STRIDE + 8);
                    al[0] = lds32(Al + ra);         al[1] = lds32(Al + ra + 8 * SA_STRIDE);
                    al[2] = lds32(Al + ra + 8);     al[3] = lds32(Al + ra + 8 * SA_STRIDE + 8);
#pragma unroll
                    for (int g = 0; g < 3; g++) {
                        const int rb = (g * 8 + gq) * SW_STRIDE + ch * 128 + kk + tg * 2;
                        uint32_t bh[2] = { lds32(sWh + rb), lds32(sWh + rb + 8) };
                        uint32_t bl[2] = { lds32(sWl + rb), lds32(sWl + rb + 8) };
                        mma_bf16(c0[g], ah, bh);
                        mma_bf16(c1[g], ah, bl);
                        mma_bf16(c0[g], al, bh);
                    }
                }
                if (ch < 7) stage_store(r, sA, buf ^ 1, tid);
                __syncthreads();
            }
        }

        // stash accumulators: sAcc[ks][gate][b][c] (unique slots per thread)
        {
            const int r0 = mt * 16 + gq;
#pragma unroll
            for (int g = 0; g < 3; g++) {
                float* sa = sAcc + ks * 1536 + g * 512;
                sa[r0 * 8 + tg * 2]           = c0[g][0] + c1[g][0];
                sa[r0 * 8 + tg * 2 + 1]       = c0[g][1] + c1[g][1];
                sa[(r0 + 8) * 8 + tg * 2]     = c0[g][2] + c1[g][2];
                sa[(r0 + 8) * 8 + tg * 2 + 1] = c0[g][3] + c1[g][3];
            }
        }
        __syncthreads();

        // fused gates + h update (h_prev from smem, written by same thread at t-1)
#pragma unroll
        for (int q = 0; q < 2; q++) {
            const int idx = tid + q * 256;
            const int b = idx >> 3, c = idx & 7;
            const int h = h0 + c;
            const float ar = sAcc[idx] + sAcc[1536 + idx];
            const float az = sAcc[512 + idx] + sAcc[1536 + 512 + idx];
            const float an = sAcc[1024 + idx] + sAcc[1536 + 1024 + idx];
            const float hp = (t > 0) ? sH[idx] : 0.f;
            const float rg = 1.f / (1.f + __expf(-(pxr[q] + ar)));
            const float zg = 1.f / (1.f + __expf(-(pxz[q] + az)));
            const float nn = tanhf(pxn[q] + rg * an);
            const float hn = (1.f - zg) * nn + zg * hp;
            sH[idx] = hn;
            out_hs[((size_t)b * TT + t) * HD + h] = hn;
            const __nv_bfloat16 hi = __float2bfloat16_rn(hn);
            const float lo = hn - __bfloat162float(hi);
            const int p = t & 1;
            g_hh[p * BB * HD + b * HD + h] = hi;
            g_hl[p * BB * HD + b * HD + h] = __float2bfloat16_rn(lo);
            if (t == TT - 1) out_last[b * HD + h] = hn;
        }

        if (t + 1 < TT) gridbar((unsigned)GCTA * (unsigned)(t + 1));
    }
}

// ---------------- launcher ------------------------------------------------
extern "C" void kernel_launch(void* const* d_in, const int* in_sizes, int n_in,
                              void* d_out, int out_size) {
    const float* x   = (const float*)d_in[0];
    const float* wxr = (const float*)d_in[1];
    const float* bxr = (const float*)d_in[2];
    const float* whr = (const float*)d_in[3];
    const float* wxz = (const float*)d_in[4];
    const float* bxz = (const float*)d_in[5];
    const float* whz = (const float*)d_in[6];
    const float* wxn = (const float*)d_in[7];
    const float* bxn = (const float*)d_in[8];
    const float* whn = (const float*)d_in[9];

    float* out      = (float*)d_out;
    float* out_last = out;                 // [64,1024]
    float* out_hs   = out + 64 * 1024;     // [64,512,1024]

    cudaFuncSetAttribute(k_scan, cudaFuncAttributeMaxDynamicSharedMemorySize, SMEM_SCAN);

    k_prep<<<1024, 256>>>(x, wxr, wxz, wxn, whr, whz, whn);
    k_proj<<<dim3(16, 512, 3), 256>>>(bxr, bxz, bxn);
    k_init<<<1, 1>>>();
    k_scan<<<GCTA, 256, SMEM_SCAN>>>(out_last, out_hs);
}

// round 7
// speedup vs baseline: 2.0673x; 1.0030x over previous
#include <cuda_runtime.h>
#include <cuda_bf16.h>
#include <cstdint>

#define HD   1024
#define TT   512
#define BB   64
#define IND  512
#define BT   32768            // BB*TT
#define GCTA 128              // scan CTAs
#define XG   33554432ull      // TT*BB*HD (per-gate xbuf stride)

// ---------------- device scratch (no allocs allowed) ----------------------
__device__ __align__(16) __nv_bfloat16 g_xhi[(size_t)BT * IND];
__device__ __align__(16) __nv_bfloat16 g_xlo[(size_t)BT * IND];
__device__ __align__(16) __nv_bfloat16 g_wxhi[3u * HD * IND];
__device__ __align__(16) __nv_bfloat16 g_wxlo[3u * HD * IND];
__device__ __align__(16) __nv_bfloat16 g_whhi[3u * HD * HD];
__device__ __align__(16) __nv_bfloat16 g_whlo[3u * HD * HD];
__device__ __align__(16) float         g_xbuf[3ull * TT * BB * HD];   // [gate][t][b][h]
__device__ __align__(16) __nv_bfloat16 g_hh[2 * BB * HD];             // h split, double buf
__device__ __align__(16) __nv_bfloat16 g_hl[2 * BB * HD];
__device__ unsigned g_cnt;                                            // monotonic barrier counter

// ---------------- helpers -------------------------------------------------
__device__ __forceinline__ uint32_t lds32(const __nv_bfloat16* p) {
    return *(const uint32_t*)p;
}

__device__ __forceinline__ void mma_bf16(float c[4], const uint32_t a[4], const uint32_t b[2]) {
    asm volatile(
        "mma.sync.aligned.m16n8k16.row.col.f32.bf16.bf16.f32 "
        "{%0,%1,%2,%3}, {%4,%5,%6,%7}, {%8,%9}, {%0,%1,%2,%3};\n"
        : "+f"(c[0]), "+f"(c[1]), "+f"(c[2]), "+f"(c[3])
        : "r"(a[0]), "r"(a[1]), "r"(a[2]), "r"(a[3]), "r"(b[0]), "r"(b[1]));
}

// monotonic barrier: arrive = fenced atomicAdd (release-equivalent),
// poll = ld.acquire.gpu (plain L2 load -> no atomic-ALU serialization).
__device__ __forceinline__ void gridbar(unsigned target) {
    __syncthreads();
    if (threadIdx.x == 0) {
        __threadfence();
        atomicAdd(&g_cnt, 1u);
        unsigned v;
        do {
            asm volatile("ld.acquire.gpu.u32 %0, [%1];" : "=r"(v) : "l"(&g_cnt) : "memory");
        } while (v < target);
        __threadfence();
    }
    __syncthreads();
}

// ---------------- prep: fp32 -> bf16 hi/lo split --------------------------
__global__ void k_prep(const float* __restrict__ x,
                       const float* __restrict__ wxr, const float* __restrict__ wxz,
                       const float* __restrict__ wxn,
                       const float* __restrict__ whr, const float* __restrict__ whz,
                       const float* __restrict__ whn) {
    const unsigned N0 = (unsigned)BT * IND;
    const unsigned N1 = HD * IND;
    const unsigned N2 = HD * HD;
    const unsigned TOT = N0 + 3u * N1 + 3u * N2;
    for (unsigned i = blockIdx.x * blockDim.x + threadIdx.x; i < TOT;
         i += gridDim.x * blockDim.x) {
        float v;
        __nv_bfloat16 *dh, *dl;
        unsigned j;
        if (i < N0) {
            v = x[i]; dh = g_xhi; dl = g_xlo; j = i;
        } else if (i < N0 + 3u * N1) {
            unsigned k = i - N0;
            unsigned gi = k / N1;
            const float* s = (gi == 0) ? wxr : (gi == 1) ? wxz : wxn;
            v = s[k - gi * N1]; dh = g_wxhi; dl = g_wxlo; j = k;
        } else {
            unsigned k = i - N0 - 3u * N1;
            unsigned gi = k / N2;
            const float* s = (gi == 0) ? whr : (gi == 1) ? whz : whn;
            v = s[k - gi * N2]; dh = g_whhi; dl = g_whlo; j = k;
        }
        __nv_bfloat16 hi = __float2bfloat16_rn(v);
        float lo = v - __bfloat162float(hi);
        dh[j] = hi;
        dl[j] = __float2bfloat16_rn(lo);
    }
}

// ---------------- phase 1: input projections (unchanged, passing) ---------
__global__ __launch_bounds__(256, 1)
void k_proj(const float* __restrict__ br, const float* __restrict__ bz,
            const float* __restrict__ bn) {
    __shared__ __nv_bfloat16 sAh[64 * 72], sAl[64 * 72], sBh[64 * 72], sBl[64 * 72];

    const int tid = threadIdx.x;
    const int gate = blockIdx.z;
    const unsigned m0 = blockIdx.y * 64u;
    const unsigned n0 = blockIdx.x * 64u;
    const __nv_bfloat16* Wh = g_wxhi + (size_t)gate * HD * IND;
    const __nv_bfloat16* Wl = g_wxlo + (size_t)gate * HD * IND;
    const float* bias = (gate == 0) ? br : (gate == 1) ? bz : bn;

    const int w = tid >> 5, l = tid & 31;
    const int mw = w & 3, wn = w >> 2;
    const int gq = l >> 2, tg = l & 3;

    float acc[4][4];
#pragma unroll
    for (int i = 0; i < 4; i++)
#pragma unroll
        for (int j = 0; j < 4; j++) acc[i][j] = 0.f;

    for (int kc = 0; kc < IND; kc += 64) {
        __syncthreads();
#pragma unroll
        for (int q = 0; q < 8; q++) {
            int u = tid + q * 256;
            int arr = u >> 9, v = u & 511;
            int row = v >> 3, c8 = v & 7;
            const uint4* src;
            __nv_bfloat16* dst;
            if (arr == 0) { src = (const uint4*)(g_xhi + (size_t)(m0 + row) * IND + kc + c8 * 8); dst = sAh; }
            else if (arr == 1) { src = (const uint4*)(g_xlo + (size_t)(m0 + row) * IND + kc + c8 * 8); dst = sAl; }
            else if (arr == 2) { src = (const uint4*)(Wh + (size_t)(n0 + row) * IND + kc + c8 * 8); dst = sBh; }
            else { src = (const uint4*)(Wl + (size_t)(n0 + row) * IND + kc + c8 * 8); dst = sBl; }
            *(uint4*)(dst + row * 72 + c8 * 8) = *src;
        }
        __syncthreads();
#pragma unroll
        for (int kk = 0; kk < 64; kk += 16) {
            const int ra = (mw * 16 + gq) * 72 + kk + tg * 2;
            uint32_t ah[4], al[4];
            ah[0] = lds32(sAh + ra);          ah[1] = lds32(sAh + ra + 8 * 72);
            ah[2] = lds32(sAh + ra + 8);      ah[3] = lds32(sAh + ra + 8 * 72 + 8);
            al[0] = lds32(sAl + ra);          al[1] = lds32(sAl + ra + 8 * 72);
            al[2] = lds32(sAl + ra + 8);      al[3] = lds32(sAl + ra + 8 * 72 + 8);
#pragma unroll
            for (int t8 = 0; t8 < 4; t8++) {
                const int rb = (wn * 32 + t8 * 8 + gq) * 72 + kk + tg * 2;
                uint32_t bh[2] = { lds32(sBh + rb), lds32(sBh + rb + 8) };
                uint32_t bl[2] = { lds32(sBl + rb), lds32(sBl + rb + 8) };
                mma_bf16(acc[t8], ah, bh);
                mma_bf16(acc[t8], ah, bl);
                mma_bf16(acc[t8], al, bh);
            }
        }
    }

#pragma unroll
    for (int t8 = 0; t8 < 4; t8++) {
        unsigned col = n0 + wn * 32 + t8 * 8 + tg * 2;
        float b0 = bias[col], b1 = bias[col + 1];
        unsigned r0 = m0 + mw * 16 + gq;
        {
            unsigned b = r0 >> 9, tl = r0 & 511;
            float* o = g_xbuf + (size_t)gate * XG + (((size_t)tl * 64 + b) << 10) + col;
            o[0] = acc[t8][0] + b0;
            o[1] = acc[t8][1] + b1;
        }
        {
            unsigned r1 = r0 + 8;
            unsigned b = r1 >> 9, tl = r1 & 511;
            float* o = g_xbuf + (size_t)gate * XG + (((size_t)tl * 64 + b) << 10) + col;
            o[0] = acc[t8][2] + b0;
            o[1] = acc[t8][3] + b1;
        }
    }
}

// ---------------- barrier init (each replay) ------------------------------
__global__ void k_init() { g_cnt = 0u; }

// ---------------- phase 2: persistent recurrence --------------------------
// 128 CTAs x 512 threads (16 warps). CTA owns 8 h-cols -> N=24 (3 gates x 8).
// Warp (mt = w&3, ks = w>>2 in 0..3): m16 rows mt*16.., n=24 (all gates),
// k-quarter ks (within-chunk offsets ks*32). All 16 warps active every chunk.
// Cross-warp k-reduction via 4 sAcc slots, summed in epilogue.
#define SW_STRIDE 1032
#define SA_STRIDE 136
#define SA_ELEMS  (64 * SA_STRIDE)          // 8704

// smem: W hi/lo + A double-buf + acc[4][3][512] + hprev[512]
#define SMEM_SCAN (2*24*SW_STRIDE*2 + 4*SA_ELEMS*2 + 4*3*512*4 + 512*4)

// staging: 64 rows x 128 cols x {hi,lo} = 2048 uint4 loads, 4 per thread.
__device__ __forceinline__ void stage_load(const __nv_bfloat16* __restrict__ Hh,
                                           const __nv_bfloat16* __restrict__ Hl,
                                           uint4 r[4], int kc, int tid) {
#pragma unroll
    for (int q = 0; q < 4; q++) {
        int u = tid + q * 512;
        int arr = u >> 10, v = u & 1023;
        int row = v >> 4, c = v & 15;
        r[q] = __ldcg((const uint4*)((arr ? Hl : Hh) + (size_t)row * HD + kc + c * 8));
    }
}

__device__ __forceinline__ void stage_store(const uint4 r[4], __nv_bfloat16* sA,
                                            int buf, int tid) {
#pragma unroll
    for (int q = 0; q < 4; q++) {
        int u = tid + q * 512;
        int arr = u >> 10, v = u & 1023;
        int row = v >> 4, c = v & 15;
        *(uint4*)(sA + (size_t)(buf * 2 + arr) * SA_ELEMS + row * SA_STRIDE + c * 8) = r[q];
    }
}

__global__ __launch_bounds__(512, 1)
void k_scan(float* __restrict__ out_last, float* __restrict__ out_hs) {
    extern __shared__ char smem[];
    __nv_bfloat16* sWh = (__nv_bfloat16*)smem;                 // 24 x 1032
    __nv_bfloat16* sWl = sWh + 24 * SW_STRIDE;
    __nv_bfloat16* sA  = sWl + 24 * SW_STRIDE;                 // [2 buf][2 hl][64*136]
    float* sAcc = (float*)(sA + 4 * SA_ELEMS);                 // [4 ks][3 gate][64][8]
    float* sH   = sAcc + 4 * 3 * 512;                          // h_prev slice [64][8]

    const int tid = threadIdx.x;
    const int w = tid >> 5, l = tid & 31;
    const int mt = w & 3, ks = w >> 2;       // m-tile, k-quarter
    const int gq = l >> 2, tg = l & 3;
    const unsigned h0 = blockIdx.x * 8u;

    // load this CTA's Wh hi/lo slice once (24 rows x 1024)
    for (int u = tid; u < 6144; u += 512) {
        int arr = (u >= 3072);
        int v = arr ? (u - 3072) : u;
        int r = v >> 7, c16 = v & 127;
        size_t grow = (size_t)(r >> 3) * HD + h0 + (r & 7);    // gate*HD + col
        const uint4* src = (const uint4*)((arr ? g_whlo : g_whhi) + grow * HD + c16 * 8);
        __nv_bfloat16* dst = (arr ? sWl : sWh) + r * SW_STRIDE + c16 * 8;
        *(uint4*)dst = *src;
    }
    __syncthreads();

    const int kbase = ks * 32;               // within-chunk kk offset for this warp

    for (int t = 0; t < TT; t++) {
        float c0[3][4], c1[3][4];
#pragma unroll
        for (int g = 0; g < 3; g++)
#pragma unroll
            for (int j = 0; j < 4; j++) { c0[g][j] = 0.f; c1[g][j] = 0.f; }

        // x-gate prefetch (one element per thread; hidden behind MMA loop)
        float pxr, pxz, pxn;
        {
            const size_t xo = (((size_t)t * 64 + (tid >> 3)) << 10) + h0 + (tid & 7);
            pxr = g_xbuf[xo];
            pxz = g_xbuf[XG + xo];
            pxn = g_xbuf[2 * XG + xo];
        }

        if (t > 0) {
            const int p = (t - 1) & 1;
            const __nv_bfloat16* Hh = g_hh + p * BB * HD;
            const __nv_bfloat16* Hl = g_hl + p * BB * HD;
            uint4 r[4];
            stage_load(Hh, Hl, r, 0, tid);
            stage_store(r, sA, 0, tid);
            __syncthreads();
            for (int ch = 0; ch < 8; ch++) {
                const int buf = ch & 1;
                if (ch < 7) stage_load(Hh, Hl, r, (ch + 1) * 128, tid);  // hidden behind compute
                const __nv_bfloat16* Ah = sA + (size_t)(buf * 2) * SA_ELEMS;
                const __nv_bfloat16* Al = Ah + SA_ELEMS;
#pragma unroll
                for (int kk2 = 0; kk2 < 32; kk2 += 16) {
                    const int kk = kbase + kk2;
                    const int ra = (mt * 16 + gq) * SA_STRIDE + kk + tg * 2;
                    uint32_t ah[4], al[4];
                    ah[0] = lds32(Ah + ra);         ah[1] = lds32(Ah + ra + 8 * SA_STRIDE);
                    ah[2] = lds32(Ah + ra + 8);     ah[3] = lds32(Ah + ra + 8 * SA_STRIDE + 8);
                    al[0] = lds32(Al + ra);         al[1] = lds32(Al + ra + 8 * SA_STRIDE);
                    al[2] = lds32(Al + ra + 8);     al[3] = lds32(Al + ra + 8 * SA_STRIDE + 8);
#pragma unroll
                    for (int g = 0; g < 3; g++) {
                        const int rb = (g * 8 + gq) * SW_STRIDE + ch * 128 + kk + tg * 2;
                        uint32_t bh[2] = { lds32(sWh + rb), lds32(sWh + rb + 8) };
                        uint32_t bl[2] = { lds32(sWl + rb), lds32(sWl + rb + 8) };
                        mma_bf16(c0[g], ah, bh);
                        mma_bf16(c1[g], ah, bl);
                        mma_bf16(c0[g], al, bh);
                    }
                }
                if (ch < 7) stage_store(r, sA, buf ^ 1, tid);
                __syncthreads();
            }
        }

        // stash accumulators: sAcc[ks][gate][b][c] (unique slots per thread)
        {
            const int r0 = mt * 16 + gq;
#pragma unroll
            for (int g = 0; g < 3; g++) {
                float* sa = sAcc + ks * 1536 + g * 512;
                sa[r0 * 8 + tg * 2]           = c0[g][0] + c1[g][0];
                sa[r0 * 8 + tg * 2 + 1]       = c0[g][1] + c1[g][1];
                sa[(r0 + 8) * 8 + tg * 2]     = c0[g][2] + c1[g][2];
                sa[(r0 + 8) * 8 + tg * 2 + 1] = c0[g][3] + c1[g][3];
            }
        }
        __syncthreads();

        // fused gates + h update (exactly one element per thread)
        {
            const int idx = tid;
            const int b = idx >> 3, c = idx & 7;
            const int h = h0 + c;
            const float ar = sAcc[idx] + sAcc[1536 + idx] + sAcc[3072 + idx] + sAcc[4608 + idx];
            const float az = sAcc[512 + idx] + sAcc[1536 + 512 + idx] + sAcc[3072 + 512 + idx] + sAcc[4608 + 512 + idx];
            const float an = sAcc[1024 + idx] + sAcc[1536 + 1024 + idx] + sAcc[3072 + 1024 + idx] + sAcc[4608 + 1024 + idx];
            const float hp = (t > 0) ? sH[idx] : 0.f;
            const float rg = 1.f / (1.f + __expf(-(pxr + ar)));
            const float zg = 1.f / (1.f + __expf(-(pxz + az)));
            const float nn = tanhf(pxn + rg * an);
            const float hn = (1.f - zg) * nn + zg * hp;
            sH[idx] = hn;
            out_hs[((size_t)b * TT + t) * HD + h] = hn;
            const __nv_bfloat16 hi = __float2bfloat16_rn(hn);
            const float lo = hn - __bfloat162float(hi);
            const int p = t & 1;
            g_hh[p * BB * HD + b * HD + h] = hi;
            g_hl[p * BB * HD + b * HD + h] = __float2bfloat16_rn(lo);
            if (t == TT - 1) out_last[b * HD + h] = hn;
        }

        if (t + 1 < TT) gridbar((unsigned)GCTA * (unsigned)(t + 1));
    }
}

// ---------------- launcher ------------------------------------------------
extern "C" void kernel_launch(void* const* d_in, const int* in_sizes, int n_in,
                              void* d_out, int out_size) {
    const float* x   = (const float*)d_in[0];
    const float* wxr = (const float*)d_in[1];
    const float* bxr = (const float*)d_in[2];
    const float* whr = (const float*)d_in[3];
    const float* wxz = (const float*)d_in[4];
    const float* bxz = (const float*)d_in[5];
    const float* whz = (const float*)d_in[6];
    const float* wxn = (const float*)d_in[7];
    const float* bxn = (const float*)d_in[8];
    const float* whn = (const float*)d_in[9];

    float* out      = (float*)d_out;
    float* out_last = out;                 // [64,1024]
    float* out_hs   = out + 64 * 1024;     // [64,512,1024]

    cudaFuncSetAttribute(k_scan, cudaFuncAttributeMaxDynamicSharedMemorySize, SMEM_SCAN);

    k_prep<<<1024, 256>>>(x, wxr, wxz, wxn, whr, whz, whn);
    k_proj<<<dim3(16, 512, 3), 256>>>(bxr, bxz, bxn);
    k_init<<<1, 1>>>();
    k_scan<<<GCTA, 512, SMEM_SCAN>>>(out_last, out_hs);
}

// round 8
// speedup vs baseline: 2.8073x; 1.3580x over previous
#include <cuda_runtime.h>
#include <cuda_bf16.h>
#include <cstdint>

#define HD   1024
#define TT   512
#define BB   64
#define IND  512
#define BT   32768            // BB*TT
#define GCTA 128              // scan CTAs
#define XG   33554432ull      // TT*BB*HD (per-gate xbuf stride)

// ---------------- device scratch (no allocs allowed) ----------------------
__device__ __align__(16) __nv_bfloat16 g_xhi[(size_t)BT * IND];
__device__ __align__(16) __nv_bfloat16 g_xlo[(size_t)BT * IND];
__device__ __align__(16) __nv_bfloat16 g_wxhi[3u * HD * IND];
__device__ __align__(16) __nv_bfloat16 g_wxlo[3u * HD * IND];
__device__ __align__(16) __nv_bfloat16 g_whhi[3u * HD * HD];
__device__ __align__(16) __nv_bfloat16 g_whlo[3u * HD * HD];
__device__ __align__(16) float         g_xbuf[3ull * TT * BB * HD];   // [gate][t][b][h]
// h in MMA *fragment* layout: [parity][mt(4)][kslice(64)][lane(32)][reg(4)] u32
__device__ __align__(16) uint32_t g_hfh[2 * 4 * 64 * 32 * 4];
__device__ __align__(16) uint32_t g_hfl[2 * 4 * 64 * 32 * 4];
__device__ unsigned g_cnt;                                            // monotonic barrier counter

// ---------------- helpers -------------------------------------------------
__device__ __forceinline__ uint32_t lds32(const __nv_bfloat16* p) {
    return *(const uint32_t*)p;
}

__device__ __forceinline__ void mma_bf16(float c[4], const uint32_t a[4], const uint32_t b[2]) {
    asm volatile(
        "mma.sync.aligned.m16n8k16.row.col.f32.bf16.bf16.f32 "
        "{%0,%1,%2,%3}, {%4,%5,%6,%7}, {%8,%9}, {%0,%1,%2,%3};\n"
        : "+f"(c[0]), "+f"(c[1]), "+f"(c[2]), "+f"(c[3])
        : "r"(a[0]), "r"(a[1]), "r"(a[2]), "r"(a[3]), "r"(b[0]), "r"(b[1]));
}

// monotonic barrier: arrive = fenced atomicAdd, poll = ld.acquire.gpu.
__device__ __forceinline__ void gridbar(unsigned target) {
    __syncthreads();
    if (threadIdx.x == 0) {
        __threadfence();
        atomicAdd(&g_cnt, 1u);
        unsigned v;
        do {
            asm volatile("ld.acquire.gpu.u32 %0, [%1];" : "=r"(v) : "l"(&g_cnt) : "memory");
        } while (v < target);
        __threadfence();
    }
    __syncthreads();
}

// ---------------- prep: fp32 -> bf16 hi/lo split --------------------------
__global__ void k_prep(const float* __restrict__ x,
                       const float* __restrict__ wxr, const float* __restrict__ wxz,
                       const float* __restrict__ wxn,
                       const float* __restrict__ whr, const float* __restrict__ whz,
                       const float* __restrict__ whn) {
    const unsigned N0 = (unsigned)BT * IND;
    const unsigned N1 = HD * IND;
    const unsigned N2 = HD * HD;
    const unsigned TOT = N0 + 3u * N1 + 3u * N2;
    for (unsigned i = blockIdx.x * blockDim.x + threadIdx.x; i < TOT;
         i += gridDim.x * blockDim.x) {
        float v;
        __nv_bfloat16 *dh, *dl;
        unsigned j;
        if (i < N0) {
            v = x[i]; dh = g_xhi; dl = g_xlo; j = i;
        } else if (i < N0 + 3u * N1) {
            unsigned k = i - N0;
            unsigned gi = k / N1;
            const float* s = (gi == 0) ? wxr : (gi == 1) ? wxz : wxn;
            v = s[k - gi * N1]; dh = g_wxhi; dl = g_wxlo; j = k;
        } else {
            unsigned k = i - N0 - 3u * N1;
            unsigned gi = k / N2;
            const float* s = (gi == 0) ? whr : (gi == 1) ? whz : whn;
            v = s[k - gi * N2]; dh = g_whhi; dl = g_whlo; j = k;
        }
        __nv_bfloat16 hi = __float2bfloat16_rn(v);
        float lo = v - __bfloat162float(hi);
        dh[j] = hi;
        dl[j] = __float2bfloat16_rn(lo);
    }
}

// ---------------- phase 1: input projections (unchanged, passing) ---------
__global__ __launch_bounds__(256, 1)
void k_proj(const float* __restrict__ br, const float* __restrict__ bz,
            const float* __restrict__ bn) {
    __shared__ __nv_bfloat16 sAh[64 * 72], sAl[64 * 72], sBh[64 * 72], sBl[64 * 72];

    const int tid = threadIdx.x;
    const int gate = blockIdx.z;
    const unsigned m0 = blockIdx.y * 64u;
    const unsigned n0 = blockIdx.x * 64u;
    const __nv_bfloat16* Wh = g_wxhi + (size_t)gate * HD * IND;
    const __nv_bfloat16* Wl = g_wxlo + (size_t)gate * HD * IND;
    const float* bias = (gate == 0) ? br : (gate == 1) ? bz : bn;

    const int w = tid >> 5, l = tid & 31;
    const int mw = w & 3, wn = w >> 2;
    const int gq = l >> 2, tg = l & 3;

    float acc[4][4];
#pragma unroll
    for (int i = 0; i < 4; i++)
#pragma unroll
        for (int j = 0; j < 4; j++) acc[i][j] = 0.f;

    for (int kc = 0; kc < IND; kc += 64) {
        __syncthreads();
#pragma unroll
        for (int q = 0; q < 8; q++) {
            int u = tid + q * 256;
            int arr = u >> 9, v = u & 511;
            int row = v >> 3, c8 = v & 7;
            const uint4* src;
            __nv_bfloat16* dst;
            if (arr == 0) { src = (const uint4*)(g_xhi + (size_t)(m0 + row) * IND + kc + c8 * 8); dst = sAh; }
            else if (arr == 1) { src = (const uint4*)(g_xlo + (size_t)(m0 + row) * IND + kc + c8 * 8); dst = sAl; }
            else if (arr == 2) { src = (const uint4*)(Wh + (size_t)(n0 + row) * IND + kc + c8 * 8); dst = sBh; }
            else { src = (const uint4*)(Wl + (size_t)(n0 + row) * IND + kc + c8 * 8); dst = sBl; }
            *(uint4*)(dst + row * 72 + c8 * 8) = *src;
        }
        __syncthreads();
#pragma unroll
        for (int kk = 0; kk < 64; kk += 16) {
            const int ra = (mw * 16 + gq) * 72 + kk + tg * 2;
            uint32_t ah[4], al[4];
            ah[0] = lds32(sAh + ra);          ah[1] = lds32(sAh + ra + 8 * 72);
            ah[2] = lds32(sAh + ra + 8);      ah[3] = lds32(sAh + ra + 8 * 72 + 8);
            al[0] = lds32(sAl + ra);          al[1] = lds32(sAl + ra + 8 * 72);
            al[2] = lds32(sAl + ra + 8);      al[3] = lds32(sAl + ra + 8 * 72 + 8);
#pragma unroll
            for (int t8 = 0; t8 < 4; t8++) {
                const int rb = (wn * 32 + t8 * 8 + gq) * 72 + kk + tg * 2;
                uint32_t bh[2] = { lds32(sBh + rb), lds32(sBh + rb + 8) };
                uint32_t bl[2] = { lds32(sBl + rb), lds32(sBl + rb + 8) };
                mma_bf16(acc[t8], ah, bh);
                mma_bf16(acc[t8], ah, bl);
                mma_bf16(acc[t8], al, bh);
            }
        }
    }

#pragma unroll
    for (int t8 = 0; t8 < 4; t8++) {
        unsigned col = n0 + wn * 32 + t8 * 8 + tg * 2;
        float b0 = bias[col], b1 = bias[col + 1];
        unsigned r0 = m0 + mw * 16 + gq;
        {
            unsigned b = r0 >> 9, tl = r0 & 511;
            float* o = g_xbuf + (size_t)gate * XG + (((size_t)tl * 64 + b) << 10) + col;
            o[0] = acc[t8][0] + b0;
            o[1] = acc[t8][1] + b1;
        }
        {
            unsigned r1 = r0 + 8;
            unsigned b = r1 >> 9, tl = r1 & 511;
            float* o = g_xbuf + (size_t)gate * XG + (((size_t)tl * 64 + b) << 10) + col;
            o[0] = acc[t8][2] + b0;
            o[1] = acc[t8][3] + b1;
        }
    }
}

// ---------------- barrier init (each replay) ------------------------------
__global__ void k_init() { g_cnt = 0u; }

// ---------------- phase 2: persistent recurrence --------------------------
// 128 CTAs x 512 threads (16 warps). CTA owns 8 h-cols -> N=24 (3 gates x 8).
// Warp (mt = w&3, ks = w>>2): m16 rows mt*16.., n=24, k-quarter ks.
// A operands come DIRECTLY from L2 in fragment layout (g_hfh/g_hfl), written
// by the epilogue of the previous step. No A smem, no staging, no chunk syncs.
#define SW_STRIDE 1032

// smem: W hi/lo + acc[4][3][512] + hprev[512]
#define SMEM_SCAN (2*24*SW_STRIDE*2 + 4*3*512*4 + 512*4)

__global__ __launch_bounds__(512, 1)
void k_scan(float* __restrict__ out_last, float* __restrict__ out_hs) {
    extern __shared__ char smem[];
    __nv_bfloat16* sWh = (__nv_bfloat16*)smem;                 // 24 x 1032
    __nv_bfloat16* sWl = sWh + 24 * SW_STRIDE;
    float* sAcc = (float*)(sWl + 24 * SW_STRIDE);              // [4 ks][3 gate][64][8]
    float* sH   = sAcc + 4 * 3 * 512;                          // h_prev slice [64][8]

    const int tid = threadIdx.x;
    const int w = tid >> 5, l = tid & 31;
    const int mt = w & 3, ks = w >> 2;       // m-tile, k-quarter
    const int gq = l >> 2, tg = l & 3;
    const unsigned h0 = blockIdx.x * 8u;

    // load this CTA's Wh hi/lo slice once (24 rows x 1024)
    for (int u = tid; u < 6144; u += 512) {
        int arr = (u >= 3072);
        int v = arr ? (u - 3072) : u;
        int r = v >> 7, c16 = v & 127;
        size_t grow = (size_t)(r >> 3) * HD + h0 + (r & 7);    // gate*HD + col
        const uint4* src = (const uint4*)((arr ? g_whlo : g_whhi) + grow * HD + c16 * 8);
        __nv_bfloat16* dst = (arr ? sWl : sWh) + r * SW_STRIDE + c16 * 8;
        *(uint4*)dst = *src;
    }
    __syncthreads();

    // epilogue fragment-store indices for this thread's (b, h) element
    const int eb = tid >> 3, ec = tid & 7;
    const int eh = h0 + ec;
    const int e_mt = eb >> 4, e_r = eb & 15;
    const int e_s = eh >> 4, e_kk = eh & 15;
    const int e_lane = (e_r & 7) * 4 + ((e_kk >> 1) & 3);
    const int e_reg = (e_r >> 3) + 2 * (e_kk >> 3);
    const int e_pair = e_kk & 1;
    // u32 index within one parity bank
    const unsigned e_idx = ((unsigned)(e_mt * 64 + e_s) * 32 + e_lane) * 4 + e_reg;

    for (int t = 0; t < TT; t++) {
        float c0[3][4], c1[3][4];
#pragma unroll
        for (int g = 0; g < 3; g++)
#pragma unroll
            for (int j = 0; j < 4; j++) { c0[g][j] = 0.f; c1[g][j] = 0.f; }

        // x-gate prefetch (one element per thread; hidden behind MMA loop)
        float pxr, pxz, pxn;
        {
            const size_t xo = (((size_t)t * 64 + eb) << 10) + h0 + ec;
            pxr = g_xbuf[xo];
            pxz = g_xbuf[XG + xo];
            pxn = g_xbuf[2 * XG + xo];
        }

        if (t > 0) {
            const unsigned p = (unsigned)((t - 1) & 1);
            // base for this warp's m-tile within parity bank p
            const uint4* fH = (const uint4*)(g_hfh + (p * 4 + mt) * 64 * 128) + l;
            const uint4* fL = (const uint4*)(g_hfl + (p * 4 + mt) * 64 * 128) + l;
            // warp's 16 k-slices: s(q) = (q>>1)*8 + ks*2 + (q&1)
#define SLICE(q) (((q) >> 1) * 8 + ks * 2 + ((q) & 1))
            uint4 ph[2], pl[2];
            ph[0] = __ldcg(fH + SLICE(0) * 32);
            pl[0] = __ldcg(fL + SLICE(0) * 32);
            ph[1] = __ldcg(fH + SLICE(1) * 32);
            pl[1] = __ldcg(fL + SLICE(1) * 32);
#pragma unroll
            for (int q = 0; q < 16; q++) {
                const int cur = q & 1;
                const uint32_t ah[4] = { ph[cur].x, ph[cur].y, ph[cur].z, ph[cur].w };
                const uint32_t al[4] = { pl[cur].x, pl[cur].y, pl[cur].z, pl[cur].w };
                if (q + 2 < 16) {
                    ph[cur] = __ldcg(fH + SLICE(q + 2) * 32);
                    pl[cur] = __ldcg(fL + SLICE(q + 2) * 32);
                }
                const int kglob = SLICE(q) * 16;
#pragma unroll
                for (int g = 0; g < 3; g++) {
                    const int rb = (g * 8 + gq) * SW_STRIDE + kglob + tg * 2;
                    uint32_t bh[2] = { lds32(sWh + rb), lds32(sWh + rb + 8) };
                    uint32_t bl[2] = { lds32(sWl + rb), lds32(sWl + rb + 8) };
                    mma_bf16(c0[g], ah, bh);
                    mma_bf16(c1[g], ah, bl);
                    mma_bf16(c0[g], al, bh);
                }
            }
#undef SLICE
        }

        // stash accumulators: sAcc[ks][gate][b][c] (unique slots per thread)
        {
            const int r0 = mt * 16 + gq;
#pragma unroll
            for (int g = 0; g < 3; g++) {
                float* sa = sAcc + ks * 1536 + g * 512;
                sa[r0 * 8 + tg * 2]           = c0[g][0] + c1[g][0];
                sa[r0 * 8 + tg * 2 + 1]       = c0[g][1] + c1[g][1];
                sa[(r0 + 8) * 8 + tg * 2]     = c0[g][2] + c1[g][2];
                sa[(r0 + 8) * 8 + tg * 2 + 1] = c0[g][3] + c1[g][3];
            }
        }
        __syncthreads();

        // fused gates + h update (exactly one element per thread)
        {
            const int idx = tid;
            const float ar = sAcc[idx] + sAcc[1536 + idx] + sAcc[3072 + idx] + sAcc[4608 + idx];
            const float az = sAcc[512 + idx] + sAcc[1536 + 512 + idx] + sAcc[3072 + 512 + idx] + sAcc[4608 + 512 + idx];
            const float an = sAcc[1024 + idx] + sAcc[1536 + 1024 + idx] + sAcc[3072 + 1024 + idx] + sAcc[4608 + 1024 + idx];
            const float hp = (t > 0) ? sH[idx] : 0.f;
            const float rg = 1.f / (1.f + __expf(-(pxr + ar)));
            const float zg = 1.f / (1.f + __expf(-(pxz + az)));
            const float nn = tanhf(pxn + rg * an);
            const float hn = (1.f - zg) * nn + zg * hp;
            sH[idx] = hn;
            out_hs[((size_t)eb * TT + t) * HD + eh] = hn;
            const __nv_bfloat16 hi = __float2bfloat16_rn(hn);
            const float lo = hn - __bfloat162float(hi);
            const unsigned p = (unsigned)(t & 1);
            // scatter into fragment layout (2B stores, disjoint per thread)
            ((__nv_bfloat16*)g_hfh)[(p * 32768u + e_idx) * 2 + e_pair] = hi;
            ((__nv_bfloat16*)g_hfl)[(p * 32768u + e_idx) * 2 + e_pair] = __float2bfloat16_rn(lo);
            if (t == TT - 1) out_last[eb * HD + eh] = hn;
        }

        if (t + 1 < TT) gridbar((unsigned)GCTA * (unsigned)(t + 1));
    }
}

// ---------------- launcher ------------------------------------------------
extern "C" void kernel_launch(void* const* d_in, const int* in_sizes, int n_in,
                              void* d_out, int out_size) {
    const float* x   = (const float*)d_in[0];
    const float* wxr = (const float*)d_in[1];
    const float* bxr = (const float*)d_in[2];
    const float* whr = (const float*)d_in[3];
    const float* wxz = (const float*)d_in[4];
    const float* bxz = (const float*)d_in[5];
    const float* whz = (const float*)d_in[6];
    const float* wxn = (const float*)d_in[7];
    const float* bxn = (const float*)d_in[8];
    const float* whn = (const float*)d_in[9];

    float* out      = (float*)d_out;
    float* out_last = out;                 // [64,1024]
    float* out_hs   = out + 64 * 1024;     // [64,512,1024]

    cudaFuncSetAttribute(k_scan, cudaFuncAttributeMaxDynamicSharedMemorySize, SMEM_SCAN);

    k_prep<<<1024, 256>>>(x, wxr, wxz, wxn, whr, whz, whn);
    k_proj<<<dim3(16, 512, 3), 256>>>(bxr, bxz, bxn);
    k_init<<<1, 1>>>();
    k_scan<<<GCTA, 512, SMEM_SCAN>>>(out_last, out_hs);
}

// round 10
// speedup vs baseline: 3.2580x; 1.1606x over previous
#include <cuda_runtime.h>
#include <cuda_bf16.h>
#include <cuda_fp16.h>
#include <cstdint>

#define HD   1024
#define TT   512
#define BB   64
#define IND  512
#define BT   32768            // BB*TT
#define GCTA 128              // scan CTAs
#define XG   33554432ull      // TT*BB*HD (per-gate xbuf stride)

// ---------------- device scratch (no allocs allowed) ----------------------
__device__ __align__(16) __nv_bfloat16 g_xhi[(size_t)BT * IND];
__device__ __align__(16) __nv_bfloat16 g_xlo[(size_t)BT * IND];
__device__ __align__(16) __nv_bfloat16 g_wxhi[3u * HD * IND];
__device__ __align__(16) __nv_bfloat16 g_wxlo[3u * HD * IND];
__device__ __align__(16) __half        g_whhi[3u * HD * HD];          // fp16 hi
__device__ __align__(16) __half        g_whlo[3u * HD * HD];          // fp16 lo
__device__ __align__(16) float         g_xbuf[3ull * TT * BB * HD];   // [gate][t][b][h]
// h (fp16) in MMA fragment layout: [parity][mt(4)][slice(64)][lane(32)] uint4
__device__ __align__(16) uint32_t g_hf[2 * 4 * 64 * 32 * 4];
__device__ unsigned g_cnt;                                            // monotonic barrier counter

// ---------------- helpers -------------------------------------------------
__device__ __forceinline__ uint32_t lds32(const __nv_bfloat16* p) {
    return *(const uint32_t*)p;
}

__device__ __forceinline__ void mma_bf16(float c[4], const uint32_t a[4], const uint32_t b[2]) {
    asm volatile(
        "mma.sync.aligned.m16n8k16.row.col.f32.bf16.bf16.f32 "
        "{%0,%1,%2,%3}, {%4,%5,%6,%7}, {%8,%9}, {%0,%1,%2,%3};\n"
        : "+f"(c[0]), "+f"(c[1]), "+f"(c[2]), "+f"(c[3])
        : "r"(a[0]), "r"(a[1]), "r"(a[2]), "r"(a[3]), "r"(b[0]), "r"(b[1]));
}

__device__ __forceinline__ void mma_f16(float c[4], const uint32_t a[4], uint32_t b0, uint32_t b1) {
    asm volatile(
        "mma.sync.aligned.m16n8k16.row.col.f32.f16.f16.f32 "
        "{%0,%1,%2,%3}, {%4,%5,%6,%7}, {%8,%9}, {%0,%1,%2,%3};\n"
        : "+f"(c[0]), "+f"(c[1]), "+f"(c[2]), "+f"(c[3])
        : "r"(a[0]), "r"(a[1]), "r"(a[2]), "r"(a[3]), "r"(b0), "r"(b1));
}

__device__ __forceinline__ uint32_t pack_h2(__half a, __half b) {
    __half2 h = __halves2half2(a, b);
    return *(uint32_t*)&h;
}

// monotonic barrier: arrive = fenced atomicAdd, poll = ld.acquire.gpu.
__device__ __forceinline__ void gridbar(unsigned target) {
    __syncthreads();
    if (threadIdx.x == 0) {
        __threadfence();
        atomicAdd(&g_cnt, 1u);
        unsigned v;
        do {
            asm volatile("ld.acquire.gpu.u32 %0, [%1];" : "=r"(v) : "l"(&g_cnt) : "memory");
        } while (v < target);
        __threadfence();
    }
    __syncthreads();
}

// ---------------- prep: fp32 -> split (bf16 for x/Wx, fp16 for Wh) --------
__global__ void k_prep(const float* __restrict__ x,
                       const float* __restrict__ wxr, const float* __restrict__ wxz,
                       const float* __restrict__ wxn,
                       const float* __restrict__ whr, const float* __restrict__ whz,
                       const float* __restrict__ whn) {
    const unsigned N0 = (unsigned)BT * IND;
    const unsigned N1 = HD * IND;
    const unsigned N2 = HD * HD;
    const unsigned TOT = N0 + 3u * N1 + 3u * N2;
    for (unsigned i = blockIdx.x * blockDim.x + threadIdx.x; i < TOT;
         i += gridDim.x * blockDim.x) {
        if (i < N0) {
            float v = x[i];
            __nv_bfloat16 hi = __float2bfloat16_rn(v);
            g_xhi[i] = hi;
            g_xlo[i] = __float2bfloat16_rn(v - __bfloat162float(hi));
        } else if (i < N0 + 3u * N1) {
            unsigned k = i - N0;
            unsigned gi = k / N1;
            const float* s = (gi == 0) ? wxr : (gi == 1) ? wxz : wxn;
            float v = s[k - gi * N1];
            __nv_bfloat16 hi = __float2bfloat16_rn(v);
            g_wxhi[k] = hi;
            g_wxlo[k] = __float2bfloat16_rn(v - __bfloat162float(hi));
        } else {
            unsigned k = i - N0 - 3u * N1;
            unsigned gi = k / N2;
            const float* s = (gi == 0) ? whr : (gi == 1) ? whz : whn;
            float v = s[k - gi * N2];
            __half hi = __float2half_rn(v);
            g_whhi[k] = hi;
            g_whlo[k] = __float2half_rn(v - __half2float(hi));
        }
    }
}

// ---------------- phase 1: input projections (unchanged, passing) ---------
__global__ __launch_bounds__(256, 1)
void k_proj(const float* __restrict__ br, const float* __restrict__ bz,
            const float* __restrict__ bn) {
    __shared__ __nv_bfloat16 sAh[64 * 72], sAl[64 * 72], sBh[64 * 72], sBl[64 * 72];

    const int tid = threadIdx.x;
    const int gate = blockIdx.z;
    const unsigned m0 = blockIdx.y * 64u;
    const unsigned n0 = blockIdx.x * 64u;
    const __nv_bfloat16* Wh = g_wxhi + (size_t)gate * HD * IND;
    const __nv_bfloat16* Wl = g_wxlo + (size_t)gate * HD * IND;
    const float* bias = (gate == 0) ? br : (gate == 1) ? bz : bn;

    const int w = tid >> 5, l = tid & 31;
    const int mw = w & 3, wn = w >> 2;
    const int gq = l >> 2, tg = l & 3;

    float acc[4][4];
#pragma unroll
    for (int i = 0; i < 4; i++)
#pragma unroll
        for (int j = 0; j < 4; j++) acc[i][j] = 0.f;

    for (int kc = 0; kc < IND; kc += 64) {
        __syncthreads();
#pragma unroll
        for (int q = 0; q < 8; q++) {
            int u = tid + q * 256;
            int arr = u >> 9, v = u & 511;
            int row = v >> 3, c8 = v & 7;
            const uint4* src;
            __nv_bfloat16* dst;
            if (arr == 0) { src = (const uint4*)(g_xhi + (size_t)(m0 + row) * IND + kc + c8 * 8); dst = sAh; }
            else if (arr == 1) { src = (const uint4*)(g_xlo + (size_t)(m0 + row) * IND + kc + c8 * 8); dst = sAl; }
            else if (arr == 2) { src = (const uint4*)(Wh + (size_t)(n0 + row) * IND + kc + c8 * 8); dst = sBh; }
            else { src = (const uint4*)(Wl + (size_t)(n0 + row) * IND + kc + c8 * 8); dst = sBl; }
            *(uint4*)(dst + row * 72 + c8 * 8) = *src;
        }
        __syncthreads();
#pragma unroll
        for (int kk = 0; kk < 64; kk += 16) {
            const int ra = (mw * 16 + gq) * 72 + kk + tg * 2;
            uint32_t ah[4], al[4];
            ah[0] = lds32(sAh + ra);          ah[1] = lds32(sAh + ra + 8 * 72);
            ah[2] = lds32(sAh + ra + 8);      ah[3] = lds32(sAh + ra + 8 * 72 + 8);
            al[0] = lds32(sAl + ra);          al[1] = lds32(sAl + ra + 8 * 72);
            al[2] = lds32(sAl + ra + 8);      al[3] = lds32(sAl + ra + 8 * 72 + 8);
#pragma unroll
            for (int t8 = 0; t8 < 4; t8++) {
                const int rb = (wn * 32 + t8 * 8 + gq) * 72 + kk + tg * 2;
                uint32_t bh[2] = { lds32(sBh + rb), lds32(sBh + rb + 8) };
                uint32_t bl[2] = { lds32(sBl + rb), lds32(sBl + rb + 8) };
                mma_bf16(acc[t8], ah, bh);
                mma_bf16(acc[t8], ah, bl);
                mma_bf16(acc[t8], al, bh);
            }
        }
    }

#pragma unroll
    for (int t8 = 0; t8 < 4; t8++) {
        unsigned col = n0 + wn * 32 + t8 * 8 + tg * 2;
        float b0 = bias[col], b1 = bias[col + 1];
        unsigned r0 = m0 + mw * 16 + gq;
        {
            unsigned b = r0 >> 9, tl = r0 & 511;
            float* o = g_xbuf + (size_t)gate * XG + (((size_t)tl * 64 + b) << 10) + col;
            o[0] = acc[t8][0] + b0;
            o[1] = acc[t8][1] + b1;
        }
        {
            unsigned r1 = r0 + 8;
            unsigned b = r1 >> 9, tl = r1 & 511;
            float* o = g_xbuf + (size_t)gate * XG + (((size_t)tl * 64 + b) << 10) + col;
            o[0] = acc[t8][2] + b0;
            o[1] = acc[t8][3] + b1;
        }
    }
}

// ---------------- barrier init (each replay) ------------------------------
__global__ void k_init() { g_cnt = 0u; }

// ---------------- phase 2: persistent recurrence --------------------------
// 128 CTAs x 512 threads (16 warps = 2 mt-pairs x 8 k-slots).
// Warp (mtp = w&1, ks = w>>1): computes m-tiles {mtp*2, mtp*2+1} (m32) for
// n=24 (3 gates x 8) over 8 k-slices s = q*8+ks. B fragment loaded ONCE per
// (gate, slice) and reused for both m-tiles. A (h, fp16) direct from L2 in
// fragment layout. W pre-packed fp16 hi/lo fragments in smem (one LDS.128).
// D = A*Whi + A*Wlo accumulated into ONE fp32 chain per (mt, gate).

// smem: Wf frags (3*64*32 uint4 = 96KB) + sAcc[8][3][512] + sH[512]
#define SMEM_SCAN (3*64*32*16 + 8*3*512*4 + 512*4)

__global__ __launch_bounds__(512, 1)
void k_scan(float* __restrict__ out_last, float* __restrict__ out_hs) {
    extern __shared__ char smem[];
    uint4* sWf  = (uint4*)smem;                        // [gate][slice][lane]
    float* sAcc = (float*)(smem + 3 * 64 * 32 * 16);   // [8 ks][3 gate][64][8]
    float* sH   = sAcc + 8 * 3 * 512;                  // h_prev slice [64][8]

    const int tid = threadIdx.x;
    const int w = tid >> 5, l = tid & 31;
    const int mtp = w & 1, ks = w >> 1;      // m-tile-pair, k-slot (0..7)
    const int mt0 = mtp * 2, mt1 = mtp * 2 + 1;
    const unsigned h0 = blockIdx.x * 8u;

    // build W fragments once: sWf[(g*64+s)*32+l] = {bh0,bh1,bl0,bl1}
    for (int e = tid; e < 6144; e += 512) {
        const int g = e >> 11, rem = e & 2047;
        const int s = rem >> 5, ll = rem & 31;
        const int lgq = ll >> 2, ltg = ll & 3;
        const __half* wh = g_whhi + ((size_t)g * HD + h0 + lgq) * HD + s * 16 + ltg * 2;
        const __half* wl = g_whlo + ((size_t)g * HD + h0 + lgq) * HD + s * 16 + ltg * 2;
        uint4 f;
        f.x = pack_h2(wh[0], wh[1]);
        f.y = pack_h2(wh[8], wh[9]);
        f.z = pack_h2(wl[0], wl[1]);
        f.w = pack_h2(wl[8], wl[9]);
        sWf[(g * 64 + s) * 32 + ll] = f;
    }
    __syncthreads();

    // epilogue fragment-store indices for this thread's (b, h) element
    const int eb = tid >> 3, ec = tid & 7;
    const int eh = h0 + ec;
    const int e_mt = eb >> 4, e_r = eb & 15;
    const int e_s = eh >> 4, e_kk = eh & 15;
    const int e_lane = (e_r & 7) * 4 + ((e_kk >> 1) & 3);
    const int e_reg = (e_r >> 3) + 2 * (e_kk >> 3);
    const int e_pair = e_kk & 1;
    // half index within one parity bank (bank = 4*64*32 uint4 = 65536 halves)
    const unsigned e_half = (((unsigned)(e_mt * 64 + e_s) * 32 + e_lane) * 8) + e_reg * 2 + e_pair;

    const int gq = l >> 2, tg = l & 3;
    (void)gq; (void)tg;

    for (int t = 0; t < TT; t++) {
        float c[2][3][4];
#pragma unroll
        for (int m = 0; m < 2; m++)
#pragma unroll
            for (int g = 0; g < 3; g++)
#pragma unroll
                for (int j = 0; j < 4; j++) c[m][g][j] = 0.f;

        // x-gate prefetch (one element per thread; hidden behind MMA loop)
        float pxr, pxz, pxn;
        {
            const size_t xo = (((size_t)t * 64 + eb) << 10) + h0 + ec;
            pxr = g_xbuf[xo];
            pxz = g_xbuf[XG + xo];
            pxn = g_xbuf[2 * XG + xo];
        }

        if (t > 0) {
            const unsigned p = (unsigned)((t - 1) & 1);
            const uint4* fA0 = (const uint4*)g_hf + ((p * 4 + mt0) * 64) * 32 + l;
            const uint4* fA1 = (const uint4*)g_hf + ((p * 4 + mt1) * 64) * 32 + l;
            // slices for this warp: s(q) = q*8 + ks
            uint4 pa0[2], pa1[2];
            pa0[0] = __ldcg(fA0 + (0 * 8 + ks) * 32);
            pa1[0] = __ldcg(fA1 + (0 * 8 + ks) * 32);
            pa0[1] = __ldcg(fA0 + (1 * 8 + ks) * 32);
            pa1[1] = __ldcg(fA1 + (1 * 8 + ks) * 32);
#pragma unroll
            for (int q = 0; q < 8; q++) {
                const int cur = q & 1;
                const uint32_t a0[4] = { pa0[cur].x, pa0[cur].y, pa0[cur].z, pa0[cur].w };
                const uint32_t a1[4] = { pa1[cur].x, pa1[cur].y, pa1[cur].z, pa1[cur].w };
                if (q + 2 < 8) {
                    pa0[cur] = __ldcg(fA0 + ((q + 2) * 8 + ks) * 32);
                    pa1[cur] = __ldcg(fA1 + ((q + 2) * 8 + ks) * 32);
                }
                const int s = q * 8 + ks;
#pragma unroll
                for (int g = 0; g < 3; g++) {
                    const uint4 bf = sWf[(g * 64 + s) * 32 + l];
                    mma_f16(c[0][g], a0, bf.x, bf.y);   // A * Whi
                    mma_f16(c[0][g], a0, bf.z, bf.w);   // A * Wlo
                    mma_f16(c[1][g], a1, bf.x, bf.y);
                    mma_f16(c[1][g], a1, bf.z, bf.w);
                }
            }
        }

        // stash accumulators: sAcc[ks][gate][b][c]
        {
            const int sgq = l >> 2, stg = l & 3;
#pragma unroll
            for (int m = 0; m < 2; m++) {
                const int r0 = (mtp * 2 + m) * 16 + sgq;
#pragma unroll
                for (int g = 0; g < 3; g++) {
                    float* sa = sAcc + ks * 1536 + g * 512;
                    sa[r0 * 8 + stg * 2]           = c[m][g][0];
                    sa[r0 * 8 + stg * 2 + 1]       = c[m][g][1];
                    sa[(r0 + 8) * 8 + stg * 2]     = c[m][g][2];
                    sa[(r0 + 8) * 8 + stg * 2 + 1] = c[m][g][3];
                }
            }
        }
        __syncthreads();

        // fused gates + h update (exactly one element per thread)
        {
            const int idx = tid;
            float ar = 0.f, az = 0.f, an = 0.f;
#pragma unroll
            for (int j = 0; j < 8; j++) {
                ar += sAcc[j * 1536 + idx];
                az += sAcc[j * 1536 + 512 + idx];
                an += sAcc[j * 1536 + 1024 + idx];
            }
            const float hp = (t > 0) ? sH[idx] : 0.f;
            const float rg = 1.f / (1.f + __expf(-(pxr + ar)));
            const float zg = 1.f / (1.f + __expf(-(pxz + az)));
            const float nn = tanhf(pxn + rg * an);
            const float hn = (1.f - zg) * nn + zg * hp;
            sH[idx] = hn;
            out_hs[((size_t)eb * TT + t) * HD + eh] = hn;
            const unsigned p = (unsigned)(t & 1);
            ((__half*)g_hf)[p * 65536u + e_half] = __float2half_rn(hn);   // FIXED stride
            if (t == TT - 1) out_last[eb * HD + eh] = hn;
        }

        if (t + 1 < TT) gridbar((unsigned)GCTA * (unsigned)(t + 1));
    }
}

// ---------------- launcher ------------------------------------------------
extern "C" void kernel_launch(void* const* d_in, const int* in_sizes, int n_in,
                              void* d_out, int out_size) {
    const float* x   = (const float*)d_in[0];
    const float* wxr = (const float*)d_in[1];
    const float* bxr = (const float*)d_in[2];
    const float* whr = (const float*)d_in[3];
    const float* wxz = (const float*)d_in[4];
    const float* bxz = (const float*)d_in[5];
    const float* whz = (const float*)d_in[6];
    const float* wxn = (const float*)d_in[7];
    const float* bxn = (const float*)d_in[8];
    const float* whn = (const float*)d_in[9];

    float* out      = (float*)d_out;
    float* out_last = out;                 // [64,1024]
    float* out_hs   = out + 64 * 1024;     // [64,512,1024]

    cudaFuncSetAttribute(k_scan, cudaFuncAttributeMaxDynamicSharedMemorySize, SMEM_SCAN);

    k_prep<<<1024, 256>>>(x, wxr, wxz, wxn, whr, whz, whn);
    k_proj<<<dim3(16, 512, 3), 256>>>(bxr, bxz, bxn);
    k_init<<<1, 1>>>();
    k_scan<<<GCTA, 512, SMEM_SCAN>>>(out_last, out_hs);
}

// round 12
// speedup vs baseline: 3.6413x; 1.1176x over previous
#include <cuda_runtime.h>
#include <cuda_bf16.h>
#include <cuda_fp16.h>
#include <cstdint>

#define HD   1024
#define TT   512
#define BB   64
#define IND  512
#define BT   32768            // BB*TT
#define GCTA 128              // scan CTAs
#define XG   33554432ull      // TT*BB*HD (per-gate xbuf stride)

// ---------------- device scratch (no allocs allowed) ----------------------
__device__ __align__(16) __half g_xhi[(size_t)BT * IND];              // x fp16 hi
__device__ __align__(16) __half g_xlo[(size_t)BT * IND];              // x fp16 lo
__device__ __align__(16) __half g_wx16[3u * HD * IND];                // Wx fp16 single
__device__ __align__(16) __half g_whhi[3u * HD * HD];                 // Wh fp16 hi
__device__ __align__(16) __half g_whlo[3u * HD * HD];                 // Wh fp16 lo
__device__ __align__(16) float  g_xbuf[3ull * TT * BB * HD];          // [gate][t][b][h]
// h (fp16) in MMA fragment layout: [parity][mt(4)][slice(64)][lane(32)] uint4
__device__ __align__(16) uint32_t g_hf[2 * 4 * 64 * 32 * 4];
__device__ unsigned g_cnt;                                            // monotonic barrier counter

// ---------------- helpers -------------------------------------------------
__device__ __forceinline__ uint32_t lds32(const void* p) {
    return *(const uint32_t*)p;
}

__device__ __forceinline__ void mma_f16(float c[4], const uint32_t a[4], uint32_t b0, uint32_t b1) {
    asm volatile(
        "mma.sync.aligned.m16n8k16.row.col.f32.f16.f16.f32 "
        "{%0,%1,%2,%3}, {%4,%5,%6,%7}, {%8,%9}, {%0,%1,%2,%3};\n"
        : "+f"(c[0]), "+f"(c[1]), "+f"(c[2]), "+f"(c[3])
        : "r"(a[0]), "r"(a[1]), "r"(a[2]), "r"(a[3]), "r"(b0), "r"(b1));
}

__device__ __forceinline__ uint32_t pack_h2(__half a, __half b) {
    __half2 h = __halves2half2(a, b);
    return *(uint32_t*)&h;
}

// monotonic barrier: arrive = fenced atomicAdd, poll = ld.acquire.gpu.
__device__ __forceinline__ void gridbar(unsigned target) {
    __syncthreads();
    if (threadIdx.x == 0) {
        __threadfence();
        atomicAdd(&g_cnt, 1u);
        unsigned v;
        do {
            asm volatile("ld.acquire.gpu.u32 %0, [%1];" : "=r"(v) : "l"(&g_cnt) : "memory");
        } while (v < target);
        __threadfence();
    }
    __syncthreads();
}

// ---------------- prep: fp32 -> fp16 splits + barrier reset ---------------
__global__ void k_prep(const float* __restrict__ x,
                       const float* __restrict__ wxr, const float* __restrict__ wxz,
                       const float* __restrict__ wxn,
                       const float* __restrict__ whr, const float* __restrict__ whz,
                       const float* __restrict__ whn) {
    if (blockIdx.x == 0 && threadIdx.x == 0) g_cnt = 0u;   // replaces k_init
    const unsigned N0 = (unsigned)BT * IND;
    const unsigned N1 = HD * IND;
    const unsigned N2 = HD * HD;
    const unsigned TOT = N0 + 3u * N1 + 3u * N2;
    for (unsigned i = blockIdx.x * blockDim.x + threadIdx.x; i < TOT;
         i += gridDim.x * blockDim.x) {
        if (i < N0) {
            float v = x[i];
            __half hi = __float2half_rn(v);
            g_xhi[i] = hi;
            g_xlo[i] = __float2half_rn(v - __half2float(hi));
        } else if (i < N0 + 3u * N1) {
            unsigned k = i - N0;
            unsigned gi = k / N1;
            const float* s = (gi == 0) ? wxr : (gi == 1) ? wxz : wxn;
            g_wx16[k] = __float2half_rn(s[k - gi * N1]);
        } else {
            unsigned k = i - N0 - 3u * N1;
            unsigned gi = k / N2;
            const float* s = (gi == 0) ? whr : (gi == 1) ? whz : whn;
            float v = s[k - gi * N2];
            __half hi = __float2half_rn(v);
            g_whhi[k] = hi;
            g_whlo[k] = __float2half_rn(v - __half2float(hi));
        }
    }
}

// ---------------- phase 1: input projections (fp16, 2-pass) ---------------
// grid (16 n-tiles, 512 m-tiles, 3 gates), block 256 (8 warps: 4m x 2n)
// A = x hi/lo fp16 (2-pass), B = Wx single fp16.
__global__ __launch_bounds__(256, 1)
void k_proj(const float* __restrict__ br, const float* __restrict__ bz,
            const float* __restrict__ bn) {
    __shared__ __half sAh[64 * 72], sAl[64 * 72], sB[64 * 72];

    const int tid = threadIdx.x;
    const int gate = blockIdx.z;
    const unsigned m0 = blockIdx.y * 64u;
    const unsigned n0 = blockIdx.x * 64u;
    const __half* W = g_wx16 + (size_t)gate * HD * IND;
    const float* bias = (gate == 0) ? br : (gate == 1) ? bz : bn;

    const int w = tid >> 5, l = tid & 31;
    const int mw = w & 3, wn = w >> 2;
    const int gq = l >> 2, tg = l & 3;

    float acc[4][4];
#pragma unroll
    for (int i = 0; i < 4; i++)
#pragma unroll
        for (int j = 0; j < 4; j++) acc[i][j] = 0.f;

    for (int kc = 0; kc < IND; kc += 64) {
        __syncthreads();
        // stage 3 arrays x (64 rows x 64 fp16) = 3 x 512 16B-loads
#pragma unroll
        for (int q = 0; q < 6; q++) {
            int u = tid + q * 256;              // 0..1535
            int arr = u >> 9, v = u & 511;
            int row = v >> 3, c8 = v & 7;
            const uint4* src;
            __half* dst;
            if (arr == 0) { src = (const uint4*)(g_xhi + (size_t)(m0 + row) * IND + kc + c8 * 8); dst = sAh; }
            else if (arr == 1) { src = (const uint4*)(g_xlo + (size_t)(m0 + row) * IND + kc + c8 * 8); dst = sAl; }
            else { src = (const uint4*)(W + (size_t)(n0 + row) * IND + kc + c8 * 8); dst = sB; }
            *(uint4*)(dst + row * 72 + c8 * 8) = *src;
        }
        __syncthreads();
#pragma unroll
        for (int kk = 0; kk < 64; kk += 16) {
            const int ra = (mw * 16 + gq) * 72 + kk + tg * 2;
            uint32_t ah[4], al[4];
            ah[0] = lds32(sAh + ra);          ah[1] = lds32(sAh + ra + 8 * 72);
            ah[2] = lds32(sAh + ra + 8);      ah[3] = lds32(sAh + ra + 8 * 72 + 8);
            al[0] = lds32(sAl + ra);          al[1] = lds32(sAl + ra + 8 * 72);
            al[2] = lds32(sAl + ra + 8);      al[3] = lds32(sAl + ra + 8 * 72 + 8);
#pragma unroll
            for (int t8 = 0; t8 < 4; t8++) {
                const int rb = (wn * 32 + t8 * 8 + gq) * 72 + kk + tg * 2;
                uint32_t b0 = lds32(sB + rb), b1 = lds32(sB + rb + 8);
                mma_f16(acc[t8], ah, b0, b1);
                mma_f16(acc[t8], al, b0, b1);
            }
        }
    }

#pragma unroll
    for (int t8 = 0; t8 < 4; t8++) {
        unsigned col = n0 + wn * 32 + t8 * 8 + tg * 2;
        float b0 = bias[col], b1 = bias[col + 1];
        unsigned r0 = m0 + mw * 16 + gq;
        {
            unsigned b = r0 >> 9, tl = r0 & 511;
            float* o = g_xbuf + (size_t)gate * XG + (((size_t)tl * 64 + b) << 10) + col;
            o[0] = acc[t8][0] + b0;
            o[1] = acc[t8][1] + b1;
        }
        {
            unsigned r1 = r0 + 8;
            unsigned b = r1 >> 9, tl = r1 & 511;
            float* o = g_xbuf + (size_t)gate * XG + (((size_t)tl * 64 + b) << 10) + col;
            o[0] = acc[t8][2] + b0;
            o[1] = acc[t8][3] + b1;
        }
    }
}

// ---------------- phase 2: persistent recurrence (R10 structure) ----------
// 128 CTAs x 512 threads (16 warps = 2 mt-pairs x 8 k-slots).
// A (h, fp16) direct from L2 in fragment layout; W pre-packed fp16 hi/lo
// fragments in smem; D = A*Whi + A*Wlo in one fp32 chain per (mt, gate).

// smem: Wf frags (3*64*32 uint4 = 96KB) + sAcc[8][3][512] + sH[512]
#define SMEM_SCAN (3*64*32*16 + 8*3*512*4 + 512*4)

__global__ __launch_bounds__(512, 1)
void k_scan(float* __restrict__ out_last, float* __restrict__ out_hs) {
    extern __shared__ char smem[];
    uint4* sWf  = (uint4*)smem;                        // [gate][slice][lane]
    float* sAcc = (float*)(smem + 3 * 64 * 32 * 16);   // [8 ks][3 gate][64][8]
    float* sH   = sAcc + 8 * 3 * 512;                  // h_prev slice [64][8]

    const int tid = threadIdx.x;
    const int w = tid >> 5, l = tid & 31;
    const int mtp = w & 1, ks = w >> 1;      // m-tile-pair, k-slot (0..7)
    const int mt0 = mtp * 2, mt1 = mtp * 2 + 1;
    const unsigned h0 = blockIdx.x * 8u;

    // build W fragments once: sWf[(g*64+s)*32+l] = {bh0,bh1,bl0,bl1}
    for (int e = tid; e < 6144; e += 512) {
        const int g = e >> 11, rem = e & 2047;
        const int s = rem >> 5, ll = rem & 31;
        const int lgq = ll >> 2, ltg = ll & 3;
        const __half* wh = g_whhi + ((size_t)g * HD + h0 + lgq) * HD + s * 16 + ltg * 2;
        const __half* wl = g_whlo + ((size_t)g * HD + h0 + lgq) * HD + s * 16 + ltg * 2;
        uint4 f;
        f.x = pack_h2(wh[0], wh[1]);
        f.y = pack_h2(wh[8], wh[9]);
        f.z = pack_h2(wl[0], wl[1]);
        f.w = pack_h2(wl[8], wl[9]);
        sWf[(g * 64 + s) * 32 + ll] = f;
    }
    __syncthreads();

    // epilogue fragment-store indices for this thread's (b, h) element
    const int eb = tid >> 3, ec = tid & 7;
    const int eh = h0 + ec;
    const int e_mt = eb >> 4, e_r = eb & 15;
    const int e_s = eh >> 4, e_kk = eh & 15;
    const int e_lane = (e_r & 7) * 4 + ((e_kk >> 1) & 3);
    const int e_reg = (e_r >> 3) + 2 * (e_kk >> 3);
    const int e_pair = e_kk & 1;
    // half index within one parity bank (bank = 4*64*32 uint4 = 65536 halves)
    const unsigned e_half = (((unsigned)(e_mt * 64 + e_s) * 32 + e_lane) * 8) + e_reg * 2 + e_pair;

    for (int t = 0; t < TT; t++) {
        float c[2][3][4];
#pragma unroll
        for (int m = 0; m < 2; m++)
#pragma unroll
            for (int g = 0; g < 3; g++)
#pragma unroll
                for (int j = 0; j < 4; j++) c[m][g][j] = 0.f;

        // x-gate prefetch (one element per thread; hidden behind MMA loop)
        float pxr, pxz, pxn;
        {
            const size_t xo = (((size_t)t * 64 + eb) << 10) + h0 + ec;
            pxr = g_xbuf[xo];
            pxz = g_xbuf[XG + xo];
            pxn = g_xbuf[2 * XG + xo];
        }

        if (t > 0) {
            const unsigned p = (unsigned)((t - 1) & 1);
            const uint4* fA0 = (const uint4*)g_hf + ((p * 4 + mt0) * 64) * 32 + l;
            const uint4* fA1 = (const uint4*)g_hf + ((p * 4 + mt1) * 64) * 32 + l;
            // slices for this warp: s(q) = q*8 + ks
            uint4 pa0[2], pa1[2];
            pa0[0] = __ldcg(fA0 + (0 * 8 + ks) * 32);
            pa1[0] = __ldcg(fA1 + (0 * 8 + ks) * 32);
            pa0[1] = __ldcg(fA0 + (1 * 8 + ks) * 32);
            pa1[1] = __ldcg(fA1 + (1 * 8 + ks) * 32);
#pragma unroll
            for (int q = 0; q < 8; q++) {
                const int cur = q & 1;
                const uint32_t a0[4] = { pa0[cur].x, pa0[cur].y, pa0[cur].z, pa0[cur].w };
                const uint32_t a1[4] = { pa1[cur].x, pa1[cur].y, pa1[cur].z, pa1[cur].w };
                if (q + 2 < 8) {
                    pa0[cur] = __ldcg(fA0 + ((q + 2) * 8 + ks) * 32);
                    pa1[cur] = __ldcg(fA1 + ((q + 2) * 8 + ks) * 32);
                }
                const int s = q * 8 + ks;
#pragma unroll
                for (int g = 0; g < 3; g++) {
                    const uint4 bf = sWf[(g * 64 + s) * 32 + l];
                    mma_f16(c[0][g], a0, bf.x, bf.y);   // A * Whi
                    mma_f16(c[0][g], a0, bf.z, bf.w);   // A * Wlo
                    mma_f16(c[1][g], a1, bf.x, bf.y);
                    mma_f16(c[1][g], a1, bf.z, bf.w);
                }
            }
        }

        // stash accumulators: sAcc[ks][gate][b][c] via STS.64 (pairs contiguous)
        {
            const int sgq = l >> 2, stg = l & 3;
#pragma unroll
            for (int m = 0; m < 2; m++) {
                const int r0 = (mtp * 2 + m) * 16 + sgq;
#pragma unroll
                for (int g = 0; g < 3; g++) {
                    float* sa = sAcc + ks * 1536 + g * 512;
                    *(float2*)&sa[r0 * 8 + stg * 2]       = make_float2(c[m][g][0], c[m][g][1]);
                    *(float2*)&sa[(r0 + 8) * 8 + stg * 2] = make_float2(c[m][g][2], c[m][g][3]);
                }
            }
        }
        __syncthreads();

        // fused gates + h update (exactly one element per thread)
        {
            const int idx = tid;
            float ar = 0.f, az = 0.f, an = 0.f;
#pragma unroll
            for (int j = 0; j < 8; j++) {
                ar += sAcc[j * 1536 + idx];
                az += sAcc[j * 1536 + 512 + idx];
                an += sAcc[j * 1536 + 1024 + idx];
            }
            const float hp = (t > 0) ? sH[idx] : 0.f;
            const float rg = 1.f / (1.f + __expf(-(pxr + ar)));
            const float zg = 1.f / (1.f + __expf(-(pxz + az)));
            const float nn = tanhf(pxn + rg * an);
            const float hn = (1.f - zg) * nn + zg * hp;
            sH[idx] = hn;
            out_hs[((size_t)eb * TT + t) * HD + eh] = hn;
            const unsigned p = (unsigned)(t & 1);
            ((__half*)g_hf)[p * 65536u + e_half] = __float2half_rn(hn);
            if (t == TT - 1) out_last[eb * HD + eh] = hn;
        }

        if (t + 1 < TT) gridbar((unsigned)GCTA * (unsigned)(t + 1));
    }
}

// ---------------- launcher ------------------------------------------------
extern "C" void kernel_launch(void* const* d_in, const int* in_sizes, int n_in,
                              void* d_out, int out_size) {
    const float* x   = (const float*)d_in[0];
    const float* wxr = (const float*)d_in[1];
    const float* bxr = (const float*)d_in[2];
    const float* whr = (const float*)d_in[3];
    const float* wxz = (const float*)d_in[4];
    const float* bxz = (const float*)d_in[5];
    const float* whz = (const float*)d_in[6];
    const float* wxn = (const float*)d_in[7];
    const float* bxn = (const float*)d_in[8];
    const float* whn = (const float*)d_in[9];

    float* out      = (float*)d_out;
    float* out_last = out;                 // [64,1024]
    float* out_hs   = out + 64 * 1024;     // [64,512,1024]

    cudaFuncSetAttribute(k_scan, cudaFuncAttributeMaxDynamicSharedMemorySize, SMEM_SCAN);

    k_prep<<<1024, 256>>>(x, wxr, wxz, wxn, whr, whz, whn);
    k_proj<<<dim3(16, 512, 3), 256>>>(bxr, bxz, bxn);
    k_scan<<<GCTA, 512, SMEM_SCAN>>>(out_last, out_hs);
}

// round 14
// speedup vs baseline: 3.7090x; 1.0186x over previous
#include <cuda_runtime.h>
#include <cuda_bf16.h>
#include <cuda_fp16.h>
#include <cstdint>

#define HD   1024
#define TT   512
#define BB   64
#define IND  512
#define BT   32768            // BB*TT
#define GCTA 128              // scan CTAs
#define XG   33554432ull      // TT*BB*HD (per-gate xbuf stride)

// ---------------- device scratch (no allocs allowed) ----------------------
__device__ __align__(16) __half g_xhi[(size_t)BT * IND];              // x fp16 hi
__device__ __align__(16) __half g_xlo[(size_t)BT * IND];              // x fp16 lo
__device__ __align__(16) __half g_wx16[3u * HD * IND];                // Wx fp16 single
__device__ __align__(16) __half g_whhi[3u * HD * HD];                 // Wh fp16 hi
__device__ __align__(16) __half g_whlo[3u * HD * HD];                 // Wh fp16 lo (used for n-gate)
__device__ __align__(16) float  g_xbuf[3ull * TT * BB * HD];          // [gate][t][b][h]
// h (fp16) in MMA fragment layout: [parity][mt(4)][slice(64)][lane(32)] uint4
__device__ __align__(16) uint32_t g_hf[2 * 4 * 64 * 32 * 4];
__device__ unsigned g_cnt;                                            // monotonic barrier counter

// ---------------- helpers -------------------------------------------------
__device__ __forceinline__ uint32_t lds32(const void* p) {
    return *(const uint32_t*)p;
}

__device__ __forceinline__ void mma_f16(float c[4], const uint32_t a[4], uint32_t b0, uint32_t b1) {
    asm volatile(
        "mma.sync.aligned.m16n8k16.row.col.f32.f16.f16.f32 "
        "{%0,%1,%2,%3}, {%4,%5,%6,%7}, {%8,%9}, {%0,%1,%2,%3};\n"
        : "+f"(c[0]), "+f"(c[1]), "+f"(c[2]), "+f"(c[3])
        : "r"(a[0]), "r"(a[1]), "r"(a[2]), "r"(a[3]), "r"(b0), "r"(b1));
}

__device__ __forceinline__ uint32_t pack_h2(__half a, __half b) {
    __half2 h = __halves2half2(a, b);
    return *(uint32_t*)&h;
}

// monotonic barrier. All threads fence (orders their h-fragment STGs to L2)
// BEFORE the block sync; then one thread arrives and polls with plain
// acquire loads (no atomic-ALU serialization on the poll path).
__device__ __forceinline__ void gridbar(unsigned target) {
    __threadfence();
    __syncthreads();
    if (threadIdx.x == 0) {
        atomicAdd(&g_cnt, 1u);
        unsigned v;
        do {
            asm volatile("ld.acquire.gpu.u32 %0, [%1];" : "=r"(v) : "l"(&g_cnt) : "memory");
        } while (v < target);
        __threadfence();
    }
    __syncthreads();
}

// ---------------- prep: fp32 -> fp16 splits + barrier reset ---------------
__global__ void k_prep(const float* __restrict__ x,
                       const float* __restrict__ wxr, const float* __restrict__ wxz,
                       const float* __restrict__ wxn,
                       const float* __restrict__ whr, const float* __restrict__ whz,
                       const float* __restrict__ whn) {
    if (blockIdx.x == 0 && threadIdx.x == 0) g_cnt = 0u;
    const unsigned N0 = (unsigned)BT * IND;
    const unsigned N1 = HD * IND;
    const unsigned N2 = HD * HD;
    const unsigned TOT = N0 + 3u * N1 + 3u * N2;
    for (unsigned i = blockIdx.x * blockDim.x + threadIdx.x; i < TOT;
         i += gridDim.x * blockDim.x) {
        if (i < N0) {
            float v = x[i];
            __half hi = __float2half_rn(v);
            g_xhi[i] = hi;
            g_xlo[i] = __float2half_rn(v - __half2float(hi));
        } else if (i < N0 + 3u * N1) {
            unsigned k = i - N0;
            unsigned gi = k / N1;
            const float* s = (gi == 0) ? wxr : (gi == 1) ? wxz : wxn;
            g_wx16[k] = __float2half_rn(s[k - gi * N1]);
        } else {
            unsigned k = i - N0 - 3u * N1;
            unsigned gi = k / N2;
            const float* s = (gi == 0) ? whr : (gi == 1) ? whz : whn;
            float v = s[k - gi * N2];
            __half hi = __float2half_rn(v);
            g_whhi[k] = hi;
            g_whlo[k] = __float2half_rn(v - __half2float(hi));
        }
    }
}

// ---------------- phase 1: input projections (fp16, 2-pass) ---------------
__global__ __launch_bounds__(256, 1)
void k_proj(const float* __restrict__ br, const float* __restrict__ bz,
            const float* __restrict__ bn) {
    __shared__ __half sAh[64 * 72], sAl[64 * 72], sB[64 * 72];

    const int tid = threadIdx.x;
    const int gate = blockIdx.z;
    const unsigned m0 = blockIdx.y * 64u;
    const unsigned n0 = blockIdx.x * 64u;
    const __half* W = g_wx16 + (size_t)gate * HD * IND;
    const float* bias = (gate == 0) ? br : (gate == 1) ? bz : bn;

    const int w = tid >> 5, l = tid & 31;
    const int mw = w & 3, wn = w >> 2;
    const int gq = l >> 2, tg = l & 3;

    float acc[4][4];
#pragma unroll
    for (int i = 0; i < 4; i++)
#pragma unroll
        for (int j = 0; j < 4; j++) acc[i][j] = 0.f;

    for (int kc = 0; kc < IND; kc += 64) {
        __syncthreads();
#pragma unroll
        for (int q = 0; q < 6; q++) {
            int u = tid + q * 256;
            int arr = u >> 9, v = u & 511;
            int row = v >> 3, c8 = v & 7;
            const uint4* src;
            __half* dst;
            if (arr == 0) { src = (const uint4*)(g_xhi + (size_t)(m0 + row) * IND + kc + c8 * 8); dst = sAh; }
            else if (arr == 1) { src = (const uint4*)(g_xlo + (size_t)(m0 + row) * IND + kc + c8 * 8); dst = sAl; }
            else { src = (const uint4*)(W + (size_t)(n0 + row) * IND + kc + c8 * 8); dst = sB; }
            *(uint4*)(dst + row * 72 + c8 * 8) = *src;
        }
        __syncthreads();
#pragma unroll
        for (int kk = 0; kk < 64; kk += 16) {
            const int ra = (mw * 16 + gq) * 72 + kk + tg * 2;
            uint32_t ah[4], al[4];
            ah[0] = lds32(sAh + ra);          ah[1] = lds32(sAh + ra + 8 * 72);
            ah[2] = lds32(sAh + ra + 8);      ah[3] = lds32(sAh + ra + 8 * 72 + 8);
            al[0] = lds32(sAl + ra);          al[1] = lds32(sAl + ra + 8 * 72);
            al[2] = lds32(sAl + ra + 8);      al[3] = lds32(sAl + ra + 8 * 72 + 8);
#pragma unroll
            for (int t8 = 0; t8 < 4; t8++) {
                const int rb = (wn * 32 + t8 * 8 + gq) * 72 + kk + tg * 2;
                uint32_t b0 = lds32(sB + rb), b1 = lds32(sB + rb + 8);
                mma_f16(acc[t8], ah, b0, b1);
                mma_f16(acc[t8], al, b0, b1);
            }
        }
    }

#pragma unroll
    for (int t8 = 0; t8 < 4; t8++) {
        unsigned col = n0 + wn * 32 + t8 * 8 + tg * 2;
        float b0 = bias[col], b1 = bias[col + 1];
        unsigned r0 = m0 + mw * 16 + gq;
        {
            unsigned b = r0 >> 9, tl = r0 & 511;
            float* o = g_xbuf + (size_t)gate * XG + (((size_t)tl * 64 + b) << 10) + col;
            o[0] = acc[t8][0] + b0;
            o[1] = acc[t8][1] + b1;
        }
        {
            unsigned r1 = r0 + 8;
            unsigned b = r1 >> 9, tl = r1 & 511;
            float* o = g_xbuf + (size_t)gate * XG + (((size_t)tl * 64 + b) << 10) + col;
            o[0] = acc[t8][2] + b0;
            o[1] = acc[t8][3] + b1;
        }
    }
}

// ---------------- phase 2: persistent recurrence --------------------------
// 128 CTAs x 512 threads (16 warps = 2 mt-pairs x 8 k-slots).
// Gate-asymmetric W precision: Whr/Whz single fp16 (sigmoid damps their
// error by <=0.25), Whn hi+lo split (tanh passes error through).
// MMAs per warp per q: 8 (was 12). A (h fp16) direct from L2 fragments.

// smem: sWrz uint2[2][64][32] (32KB) + sWn uint4[64][32] (32KB)
//       + sAcc[8][3][512] (48KB) + sH[512] (2KB)
#define SMEM_SCAN (2*64*32*8 + 64*32*16 + 8*3*512*4 + 512*4)

__global__ __launch_bounds__(512, 1)
void k_scan(float* __restrict__ out_last, float* __restrict__ out_hs) {
    extern __shared__ char smem[];
    uint2* sWrz = (uint2*)smem;                        // [gate(2)][slice][lane]
    uint4* sWn  = (uint4*)(smem + 32768);              // [slice][lane]
    float* sAcc = (float*)(smem + 65536);              // [8 ks][3 gate][64][8]
    float* sH   = sAcc + 8 * 3 * 512;                  // h_prev slice [64][8]

    const int tid = threadIdx.x;
    const int w = tid >> 5, l = tid & 31;
    const int mtp = w & 1, ks = w >> 1;      // m-tile-pair, k-slot (0..7)
    const int mt0 = mtp * 2, mt1 = mtp * 2 + 1;
    const unsigned h0 = blockIdx.x * 8u;

    // build W fragments once
    for (int e = tid; e < 6144; e += 512) {
        if (e < 4096) {
            const int g = e >> 11, rem = e & 2047;
            const int s = rem >> 5, ll = rem & 31;
            const int lgq = ll >> 2, ltg = ll & 3;
            const __half* wh = g_whhi + ((size_t)g * HD + h0 + lgq) * HD + s * 16 + ltg * 2;
            uint2 f;
            f.x = pack_h2(wh[0], wh[1]);
            f.y = pack_h2(wh[8], wh[9]);
            sWrz[(g * 64 + s) * 32 + ll] = f;
        } else {
            const int rem = e - 4096;
            const int s = rem >> 5, ll = rem & 31;
            const int lgq = ll >> 2, ltg = ll & 3;
            const __half* wh = g_whhi + ((size_t)2 * HD + h0 + lgq) * HD + s * 16 + ltg * 2;
            const __half* wl = g_whlo + ((size_t)2 * HD + h0 + lgq) * HD + s * 16 + ltg * 2;
            uint4 f;
            f.x = pack_h2(wh[0], wh[1]);
            f.y = pack_h2(wh[8], wh[9]);
            f.z = pack_h2(wl[0], wl[1]);
            f.w = pack_h2(wl[8], wl[9]);
            sWn[s * 32 + ll] = f;
        }
    }
    __syncthreads();

    // epilogue fragment-store indices for this thread's (b, h) element
    const int eb = tid >> 3, ec = tid & 7;
    const int eh = h0 + ec;
    const int e_mt = eb >> 4, e_r = eb & 15;
    const int e_s = eh >> 4, e_kk = eh & 15;
    const int e_lane = (e_r & 7) * 4 + ((e_kk >> 1) & 3);
    const int e_reg = (e_r >> 3) + 2 * (e_kk >> 3);
    const int e_pair = e_kk & 1;
    // half index within one parity bank (bank = 4*64*32 uint4 = 65536 halves)
    const unsigned e_half = (((unsigned)(e_mt * 64 + e_s) * 32 + e_lane) * 8) + e_reg * 2 + e_pair;

    for (int t = 0; t < TT; t++) {
        float c[2][3][4];
#pragma unroll
        for (int m = 0; m < 2; m++)
#pragma unroll
            for (int g = 0; g < 3; g++)
#pragma unroll
                for (int j = 0; j < 4; j++) c[m][g][j] = 0.f;

        // x-gate prefetch (one element per thread; hidden behind MMA loop)
        float pxr, pxz, pxn;
        {
            const size_t xo = (((size_t)t * 64 + eb) << 10) + h0 + ec;
            pxr = g_xbuf[xo];
            pxz = g_xbuf[XG + xo];
            pxn = g_xbuf[2 * XG + xo];
        }

        if (t > 0) {
            const unsigned p = (unsigned)((t - 1) & 1);
            const uint4* fA0 = (const uint4*)g_hf + ((p * 4 + mt0) * 64) * 32 + l;
            const uint4* fA1 = (const uint4*)g_hf + ((p * 4 + mt1) * 64) * 32 + l;
            // slices for this warp: s(q) = q*8 + ks
            uint4 pa0[2], pa1[2];
            pa0[0] = __ldcg(fA0 + (0 * 8 + ks) * 32);
            pa1[0] = __ldcg(fA1 + (0 * 8 + ks) * 32);
            pa0[1] = __ldcg(fA0 + (1 * 8 + ks) * 32);
            pa1[1] = __ldcg(fA1 + (1 * 8 + ks) * 32);
#pragma unroll
            for (int q = 0; q < 8; q++) {
                const int cur = q & 1;
                const uint32_t a0[4] = { pa0[cur].x, pa0[cur].y, pa0[cur].z, pa0[cur].w };
                const uint32_t a1[4] = { pa1[cur].x, pa1[cur].y, pa1[cur].z, pa1[cur].w };
                if (q + 2 < 8) {
                    pa0[cur] = __ldcg(fA0 + ((q + 2) * 8 + ks) * 32);
                    pa1[cur] = __ldcg(fA1 + ((q + 2) * 8 + ks) * 32);
                }
                const int s = q * 8 + ks;
                const uint2 brf = sWrz[(0 * 64 + s) * 32 + l];
                const uint2 bzf = sWrz[(1 * 64 + s) * 32 + l];
                const uint4 bnf = sWn[s * 32 + l];
                mma_f16(c[0][0], a0, brf.x, brf.y);
                mma_f16(c[1][0], a1, brf.x, brf.y);
                mma_f16(c[0][1], a0, bzf.x, bzf.y);
                mma_f16(c[1][1], a1, bzf.x, bzf.y);
                mma_f16(c[0][2], a0, bnf.x, bnf.y);   // A * Wn_hi
                mma_f16(c[0][2], a0, bnf.z, bnf.w);   // A * Wn_lo
                mma_f16(c[1][2], a1, bnf.x, bnf.y);
                mma_f16(c[1][2], a1, bnf.z, bnf.w);
            }
        }

        // stash accumulators: sAcc[ks][gate][b][c] via STS.64
        {
            const int sgq = l >> 2, stg = l & 3;
#pragma unroll
            for (int m = 0; m < 2; m++) {
                const int r0 = (mtp * 2 + m) * 16 + sgq;
#pragma unroll
                for (int g = 0; g < 3; g++) {
                    float* sa = sAcc + ks * 1536 + g * 512;
                    *(float2*)&sa[r0 * 8 + stg * 2]       = make_float2(c[m][g][0], c[m][g][1]);
                    *(float2*)&sa[(r0 + 8) * 8 + stg * 2] = make_float2(c[m][g][2], c[m][g][3]);
                }
            }
        }
        __syncthreads();

        // fused gates + h update (exactly one element per thread)
        {
            const int idx = tid;
            float ar = 0.f, az = 0.f, an = 0.f;
#pragma unroll
            for (int j = 0; j < 8; j++) {
                ar += sAcc[j * 1536 + idx];
                az += sAcc[j * 1536 + 512 + idx];
                an += sAcc[j * 1536 + 1024 + idx];
            }
            const float hp = (t > 0) ? sH[idx] : 0.f;
            const float rg = 1.f / (1.f + __expf(-(pxr + ar)));
            const float zg = 1.f / (1.f + __expf(-(pxz + az)));
            const float nn = tanhf(pxn + rg * an);
            const float hn = (1.f - zg) * nn + zg * hp;
            sH[idx] = hn;
            out_hs[((size_t)eb * TT + t) * HD + eh] = hn;
            const unsigned p = (unsigned)(t & 1);
            ((__half*)g_hf)[p * 65536u + e_half] = __float2half_rn(hn);
            if (t == TT - 1) out_last[eb * HD + eh] = hn;
        }

        if (t + 1 < TT) gridbar((unsigned)GCTA * (unsigned)(t + 1));
    }
}

// ---------------- launcher ------------------------------------------------
extern "C" void kernel_launch(void* const* d_in, const int* in_sizes, int n_in,
                              void* d_out, int out_size) {
    const float* x   = (const float*)d_in[0];
    const float* wxr = (const float*)d_in[1];
    const float* bxr = (const float*)d_in[2];
    const float* whr = (const float*)d_in[3];
    const float* wxz = (const float*)d_in[4];
    const float* bxz = (const float*)d_in[5];
    const float* whz = (const float*)d_in[6];
    const float* wxn = (const float*)d_in[7];
    const float* bxn = (const float*)d_in[8];
    const float* whn = (const float*)d_in[9];

    float* out      = (float*)d_out;
    float* out_last = out;                 // [64,1024]
    float* out_hs   = out + 64 * 1024;     // [64,512,1024]

    cudaFuncSetAttribute(k_scan, cudaFuncAttributeMaxDynamicSharedMemorySize, SMEM_SCAN);

    k_prep<<<1024, 256>>>(x, wxr, wxz, wxn, whr, whz, whn);
    k_proj<<<dim3(16, 512, 3), 256>>>(bxr, bxz, bxn);
    k_scan<<<GCTA, 512, SMEM_SCAN>>>(out_last, out_hs);
}